// round 1
// baseline (speedup 1.0000x reference)
#include <cuda_runtime.h>

#define NN 100000
#define NE 600000
#define DD 128
#define NREL 1000
#define NLAYER 3
#define SCAN_B 1024
#define SCAN_NB ((NN + SCAN_B - 1) / SCAN_B)

// ---------------- scratch (static device globals; no allocs) ----------------
__device__ float g_Q[NN * DD];
__device__ float g_K[NN * DD];
__device__ float g_V[NN * DD];
__device__ float g_S[NN * DD];
__device__ float g_Erel[NREL * DD];
__device__ float g_gsum[DD];
__device__ int g_cnt[NN];
__device__ int g_incl[NN];
__device__ int g_part[SCAN_NB];
__device__ int g_rowptr[NN + 1];
__device__ int g_cursor[NN + 1];
__device__ int g_eperm[NE];

// ---------------- f32x2 packed-FMA helpers (sm_103a) ----------------
__device__ __forceinline__ unsigned long long pack2(float lo, float hi) {
    unsigned long long r;
    asm("mov.b64 %0, {%1, %2};" : "=l"(r) : "f"(lo), "f"(hi));
    return r;
}
__device__ __forceinline__ float2 unpack2(unsigned long long v) {
    float2 r;
    asm("mov.b64 {%0, %1}, %2;" : "=f"(r.x), "=f"(r.y) : "l"(v));
    return r;
}
__device__ __forceinline__ void fma2(unsigned long long& d, unsigned long long a,
                                     unsigned long long b) {
    asm("fma.rn.f32x2 %0, %1, %2, %0;" : "+l"(d) : "l"(a), "l"(b));
}

// ---------------- init: x = ent_emb[node_ids] ----------------
__global__ void k_gather(const int* __restrict__ ids, const float* __restrict__ emb,
                         float* __restrict__ x) {
    int i = blockIdx.x * blockDim.x + threadIdx.x;  // float4 index
    if (i >= NN * 32) return;
    int n = i >> 5, l = i & 31;
    ((float4*)x)[n * 32 + l] = ((const float4*)emb)[(long long)ids[n] * 32 + l];
}

__global__ void k_zero() {
    int i = blockIdx.x * blockDim.x + threadIdx.x;
    if (i < NN) g_cnt[i] = 0;
    if (i < DD) g_gsum[i] = 0.f;
}

// ---------------- CSR build (dst-sorted) ----------------
__global__ void k_count(const int* __restrict__ dst) {
    int e = blockIdx.x * blockDim.x + threadIdx.x;
    if (e < NE) atomicAdd(&g_cnt[dst[e]], 1);
}

__global__ void k_scan1() {
    __shared__ int sh[SCAN_B];
    int i = blockIdx.x * SCAN_B + threadIdx.x;
    int v = (i < NN) ? g_cnt[i] : 0;
    sh[threadIdx.x] = v;
    __syncthreads();
    for (int off = 1; off < SCAN_B; off <<= 1) {
        int t = (threadIdx.x >= off) ? sh[threadIdx.x - off] : 0;
        __syncthreads();
        sh[threadIdx.x] += t;
        __syncthreads();
    }
    if (i < NN) g_incl[i] = sh[threadIdx.x];
    if (threadIdx.x == SCAN_B - 1) g_part[blockIdx.x] = sh[SCAN_B - 1];
}

__global__ void k_scan2() {
    if (threadIdx.x == 0 && blockIdx.x == 0) {
        int run = 0;
        for (int b = 0; b < SCAN_NB; b++) {
            int t = g_part[b];
            g_part[b] = run;
            run += t;
        }
    }
}

__global__ void k_scan3() {
    int i = blockIdx.x * SCAN_B + threadIdx.x;
    if (i < NN) {
        int v = g_incl[i] + g_part[blockIdx.x];
        g_rowptr[i + 1] = v;
        g_cursor[i + 1] = v;
        if (i == 0) { g_rowptr[0] = 0; g_cursor[0] = 0; }
    }
}

__global__ void k_scatter(const int* __restrict__ dst) {
    int e = blockIdx.x * blockDim.x + threadIdx.x;
    if (e < NE) {
        int p = atomicAdd(&g_cursor[dst[e]], 1);
        g_eperm[p] = e;
    }
}

// ---------------- per-layer: relation projection table (1000x128) ----------------
__global__ void k_erel(const float* __restrict__ rel, const float* __restrict__ We,
                       const float* __restrict__ be) {
    __shared__ float sr[DD];
    int r = blockIdx.x, j = threadIdx.x;
    sr[j] = rel[r * DD + j];
    __syncthreads();
    float acc = be[j];
#pragma unroll 8
    for (int i = 0; i < DD; i++) acc = fmaf(sr[i], We[i * DD + j], acc);
    g_Erel[r * DD + j] = acc;
}

// ---------------- fused Q/K/V/Skip SGEMM: out = x @ W + b ----------------
// 128x128 block tile, BK=8, 256 threads, 8x8 micro-tile with f32x2 FMAs.
__global__ void __launch_bounds__(256, 2)
k_qkvs(const float* __restrict__ x, const float* __restrict__ Wq, const float* __restrict__ bq,
       const float* __restrict__ Wk, const float* __restrict__ bk,
       const float* __restrict__ Wv, const float* __restrict__ bv,
       const float* __restrict__ Ws, const float* __restrict__ bs) {
    const float* W;
    const float* bias;
    float* out;
    switch (blockIdx.y) {
        case 0: W = Wq; bias = bq; out = g_Q; break;
        case 1: W = Wk; bias = bk; out = g_K; break;
        case 2: W = Wv; bias = bv; out = g_V; break;
        default: W = Ws; bias = bs; out = g_S; break;
    }
    __shared__ float sA[8][128];  // transposed x tile
    __shared__ float sB[8][128];

    int t = threadIdx.x;
    int tx = t & 15, ty = t >> 4;
    int rowBase = blockIdx.x * 128;

    unsigned long long acc[8][4];
#pragma unroll
    for (int i = 0; i < 8; i++)
#pragma unroll
        for (int j = 0; j < 4; j++) acc[i][j] = 0ull;

    int la_row = t >> 1;
    int la_k = (t & 1) * 4;
    int lb_k = t >> 5;
    int lb_col = (t & 31) * 4;

    for (int kc = 0; kc < 128; kc += 8) {
        float4 av = make_float4(0.f, 0.f, 0.f, 0.f);
        int gr = rowBase + la_row;
        if (gr < NN) av = *(const float4*)&x[(long long)gr * 128 + kc + la_k];
        sA[la_k + 0][la_row] = av.x;
        sA[la_k + 1][la_row] = av.y;
        sA[la_k + 2][la_row] = av.z;
        sA[la_k + 3][la_row] = av.w;

        *(float4*)&sB[lb_k][lb_col] = *(const float4*)&W[(kc + lb_k) * 128 + lb_col];
        __syncthreads();

#pragma unroll
        for (int k = 0; k < 8; k++) {
            float4 a0 = *(float4*)&sA[k][ty * 4];
            float4 a1 = *(float4*)&sA[k][64 + ty * 4];
            float4 b0 = *(float4*)&sB[k][tx * 4];
            float4 b1 = *(float4*)&sB[k][64 + tx * 4];
            unsigned long long bp0 = pack2(b0.x, b0.y);
            unsigned long long bp1 = pack2(b0.z, b0.w);
            unsigned long long bp2 = pack2(b1.x, b1.y);
            unsigned long long bp3 = pack2(b1.z, b1.w);
            float ar[8] = {a0.x, a0.y, a0.z, a0.w, a1.x, a1.y, a1.z, a1.w};
#pragma unroll
            for (int i = 0; i < 8; i++) {
                unsigned long long ad = pack2(ar[i], ar[i]);
                fma2(acc[i][0], ad, bp0);
                fma2(acc[i][1], ad, bp1);
                fma2(acc[i][2], ad, bp2);
                fma2(acc[i][3], ad, bp3);
            }
        }
        __syncthreads();
    }

    float4 bb0 = *(const float4*)&bias[tx * 4];
    float4 bb1 = *(const float4*)&bias[64 + tx * 4];
#pragma unroll
    for (int i = 0; i < 8; i++) {
        int rr = rowBase + ((i < 4) ? (ty * 4 + i) : (64 + ty * 4 + (i - 4)));
        if (rr >= NN) continue;
        float2 c0 = unpack2(acc[i][0]);
        float2 c1 = unpack2(acc[i][1]);
        float2 c2 = unpack2(acc[i][2]);
        float2 c3 = unpack2(acc[i][3]);
        float4 o0 = make_float4(c0.x + bb0.x, c0.y + bb0.y, c1.x + bb0.z, c1.y + bb0.w);
        float4 o1 = make_float4(c2.x + bb1.x, c2.y + bb1.y, c3.x + bb1.z, c3.y + bb1.w);
        *(float4*)&out[(long long)rr * 128 + tx * 4] = o0;
        *(float4*)&out[(long long)rr * 128 + 64 + tx * 4] = o1;
    }
}

// ---------------- fused attention / softmax / aggregate / LN / residual ----------------
// one warp per destination node; online softmax over its incoming edges.
__global__ void k_attn(float* __restrict__ x, const int* __restrict__ src,
                       const int* __restrict__ etype, const float* __restrict__ lng,
                       const float* __restrict__ lnb) {
    int n = blockIdx.x * (blockDim.x >> 5) + (threadIdx.x >> 5);
    int lane = threadIdx.x & 31;
    if (n >= NN) return;

    const float4* Q4 = (const float4*)g_Q;
    const float4* K4 = (const float4*)g_K;
    const float4* V4 = (const float4*)g_V;
    const float4* E4 = (const float4*)g_Erel;

    float4 q = Q4[n * 32 + lane];
    int beg = g_rowptr[n], end = g_rowptr[n + 1];

    float m = -3.4e38f, dsum = 0.f;
    float4 acc = make_float4(0.f, 0.f, 0.f, 0.f);

    for (int idx = beg; idx < end; idx++) {
        int e = g_eperm[idx];
        int s = src[e];
        int tt = etype[e];
        float4 ev = E4[tt * 32 + lane];
        float4 kv = K4[s * 32 + lane];
        float p = q.x * (kv.x + ev.x) + q.y * (kv.y + ev.y) + q.z * (kv.z + ev.z) +
                  q.w * (kv.w + ev.w);
        p += __shfl_xor_sync(0xffffffffu, p, 1);
        p += __shfl_xor_sync(0xffffffffu, p, 2);
        float alpha = p * 0.25f;  // 1/sqrt(16)
        float mn = fmaxf(m, alpha);
        float sc = __expf(m - mn);
        float w = __expf(alpha - mn);
        dsum = dsum * sc + w;
        float4 vv = V4[s * 32 + lane];
        acc.x = acc.x * sc + w * (vv.x + ev.x);
        acc.y = acc.y * sc + w * (vv.y + ev.y);
        acc.z = acc.z * sc + w * (vv.z + ev.z);
        acc.w = acc.w * sc + w * (vv.w + ev.w);
        m = mn;
    }

    float inv = (dsum > 0.f) ? (1.f / dsum) : 0.f;
    float4 sk = ((const float4*)g_S)[n * 32 + lane];
    float4 o = make_float4(acc.x * inv + sk.x, acc.y * inv + sk.y, acc.z * inv + sk.z,
                           acc.w * inv + sk.w);

    // LayerNorm over 128 channels (warp-wide)
    float sum = o.x + o.y + o.z + o.w;
#pragma unroll
    for (int off = 16; off; off >>= 1) sum += __shfl_xor_sync(0xffffffffu, sum, off);
    float mean = sum * (1.f / 128.f);
    float4 c = make_float4(o.x - mean, o.y - mean, o.z - mean, o.w - mean);
    float ss = c.x * c.x + c.y * c.y + c.z * c.z + c.w * c.w;
#pragma unroll
    for (int off = 16; off; off >>= 1) ss += __shfl_xor_sync(0xffffffffu, ss, off);
    float var = ss * (1.f / 128.f);
    float rstd = rsqrtf(var + 1e-5f);

    float4 g = ((const float4*)lng)[lane];
    float4 b = ((const float4*)lnb)[lane];
    float4 y;
    y.x = fmaxf(c.x * rstd * g.x + b.x, 0.f);
    y.y = fmaxf(c.y * rstd * g.y + b.y, 0.f);
    y.z = fmaxf(c.z * rstd * g.z + b.z, 0.f);
    y.w = fmaxf(c.w * rstd * g.w + b.w, 0.f);

    float4 xo = ((float4*)x)[n * 32 + lane];
    xo.x += y.x;
    xo.y += y.y;
    xo.z += y.z;
    xo.w += y.w;
    ((float4*)x)[n * 32 + lane] = xo;
}

// ---------------- graph embedding = mean over nodes ----------------
#define ROWS_PER 256
__global__ void k_colsum(const float* __restrict__ x) {
    int col = threadIdx.x;
    int rbeg = blockIdx.x * ROWS_PER;
    int rend = rbeg + ROWS_PER;
    if (rend > NN) rend = NN;
    float s = 0.f;
    for (int r = rbeg; r < rend; r++) s += x[(long long)r * DD + col];
    atomicAdd(&g_gsum[col], s);
}

__global__ void k_final(float* __restrict__ gout) {
    int c = threadIdx.x;
    if (c < DD) gout[c] = g_gsum[c] * (1.f / (float)NN);
}

// ---------------- launch ----------------
extern "C" void kernel_launch(void* const* d_in, const int* in_sizes, int n_in,
                              void* d_out, int out_size) {
    const int* node_ids = (const int*)d_in[0];
    const int* edge_index = (const int*)d_in[1];
    const int* edge_type = (const int*)d_in[2];
    const float* ent_emb = (const float*)d_in[3];
    const float* rel_emb = (const float*)d_in[4];
    const float* Wq = (const float*)d_in[5];
    const float* bq = (const float*)d_in[6];
    const float* Wk = (const float*)d_in[7];
    const float* bk = (const float*)d_in[8];
    const float* Wv = (const float*)d_in[9];
    const float* bv = (const float*)d_in[10];
    const float* We = (const float*)d_in[11];
    const float* be = (const float*)d_in[12];
    const float* Ws = (const float*)d_in[13];
    const float* bs = (const float*)d_in[14];
    const float* lng = (const float*)d_in[15];
    const float* lnb = (const float*)d_in[16];

    float* x = (float*)d_out;                       // first N*D floats
    float* gout = (float*)d_out + (out_size - DD);  // last D floats

    const int* src = edge_index;
    const int* dst = edge_index + NE;

    // init + CSR build (edges constant across layers)
    k_gather<<<(NN * 32 + 255) / 256, 256>>>(node_ids, ent_emb, x);
    k_zero<<<(NN + 255) / 256, 256>>>();
    k_count<<<(NE + 255) / 256, 256>>>(dst);
    k_scan1<<<SCAN_NB, SCAN_B>>>();
    k_scan2<<<1, 32>>>();
    k_scan3<<<SCAN_NB, SCAN_B>>>();
    k_scatter<<<(NE + 255) / 256, 256>>>(dst);

    for (int l = 0; l < NLAYER; l++) {
        long long wo = (long long)l * DD * DD;
        int bo = l * DD;
        k_erel<<<NREL, DD>>>(rel_emb, We + wo, be + bo);
        dim3 gg((NN + 127) / 128, 4);
        k_qkvs<<<gg, 256>>>(x, Wq + wo, bq + bo, Wk + wo, bk + bo, Wv + wo, bv + bo,
                            Ws + wo, bs + bo);
        k_attn<<<(NN + 7) / 8, 256>>>(x, src, edge_type, lng + bo, lnb + bo);
    }

    k_colsum<<<(NN + ROWS_PER - 1) / ROWS_PER, DD>>>(x);
    k_final<<<1, DD>>>(gout);
}

// round 3
// speedup vs baseline: 1.3887x; 1.3887x over previous
#include <cuda_runtime.h>
#include <cuda_bf16.h>
#include <cstdint>

#define NN 100000
#define NE 600000
#define DD 128
#define NREL 1000
#define NLAYER 3
#define SCAN_B 1024
#define SCAN_NB ((NN + SCAN_B - 1) / SCAN_B)

// ---------------- scratch (static device globals; no allocs) ----------------
__device__ float g_Q[NN * DD];
__device__ float g_K[NN * DD];
__device__ float g_V[NN * DD];
__device__ float g_S[NN * DD];
__device__ float g_Erel[NREL * DD];
__device__ float g_gsum[DD];
__device__ int g_cnt[NN];
__device__ int g_incl[NN];
__device__ int g_part[SCAN_NB];
__device__ int g_rowptr[NN + 1];
__device__ int g_cursor[NN + 1];
__device__ int g_eperm[NE];
// pre-swizzled bf16 W images: 12 (3 layers x {Q,K,V,S}), hi and lo parts.
// layout: B(k,n) row-major 256B rows with 16B-group xor swizzle.
__device__ __align__(16) unsigned char g_WimgH[12 * 32768];
__device__ __align__(16) unsigned char g_WimgL[12 * 32768];

__device__ __forceinline__ uint32_t smem_u32(const void* p) {
    uint32_t a;
    asm("{ .reg .u64 t; cvta.to.shared.u64 t, %1; cvt.u32.u64 %0, t; }" : "=r"(a) : "l"(p));
    return a;
}
// swizzled byte offset inside a [128 x 128bf16] tile (256B rows)
__device__ __forceinline__ int swz(int row, int g16) {
    return row * 256 + ((g16 ^ (row & 7)) << 4);
}

__device__ __forceinline__ void ldm_x4(uint32_t& r0, uint32_t& r1, uint32_t& r2, uint32_t& r3,
                                       uint32_t addr) {
    asm volatile("ldmatrix.sync.aligned.m8n8.x4.shared.b16 {%0,%1,%2,%3}, [%4];"
                 : "=r"(r0), "=r"(r1), "=r"(r2), "=r"(r3)
                 : "r"(addr));
}
__device__ __forceinline__ void ldm_x4t(uint32_t& r0, uint32_t& r1, uint32_t& r2, uint32_t& r3,
                                        uint32_t addr) {
    asm volatile("ldmatrix.sync.aligned.m8n8.x4.trans.shared.b16 {%0,%1,%2,%3}, [%4];"
                 : "=r"(r0), "=r"(r1), "=r"(r2), "=r"(r3)
                 : "r"(addr));
}
__device__ __forceinline__ void mma_bf16(float* c, uint32_t a0, uint32_t a1, uint32_t a2,
                                         uint32_t a3, uint32_t b0, uint32_t b1) {
    asm volatile(
        "mma.sync.aligned.m16n8k16.row.col.f32.bf16.bf16.f32 "
        "{%0,%1,%2,%3}, {%4,%5,%6,%7}, {%8,%9}, {%0,%1,%2,%3};"
        : "+f"(c[0]), "+f"(c[1]), "+f"(c[2]), "+f"(c[3])
        : "r"(a0), "r"(a1), "r"(a2), "r"(a3), "r"(b0), "r"(b1));
}

// ---------------- init: x = ent_emb[node_ids] ----------------
__global__ void k_gather(const int* __restrict__ ids, const float* __restrict__ emb,
                         float* __restrict__ x) {
    int i = blockIdx.x * blockDim.x + threadIdx.x;
    if (i >= NN * 32) return;
    int n = i >> 5, l = i & 31;
    ((float4*)x)[n * 32 + l] = ((const float4*)emb)[(long long)ids[n] * 32 + l];
}

__global__ void k_zero() {
    int i = blockIdx.x * blockDim.x + threadIdx.x;
    if (i < NN) g_cnt[i] = 0;
    if (i < DD) g_gsum[i] = 0.f;
}

// ---------------- CSR build (dst-sorted) ----------------
__global__ void k_count(const int* __restrict__ dst) {
    int e = blockIdx.x * blockDim.x + threadIdx.x;
    if (e < NE) atomicAdd(&g_cnt[dst[e]], 1);
}

__global__ void k_scan1() {
    __shared__ int sh[SCAN_B];
    int i = blockIdx.x * SCAN_B + threadIdx.x;
    int v = (i < NN) ? g_cnt[i] : 0;
    sh[threadIdx.x] = v;
    __syncthreads();
    for (int off = 1; off < SCAN_B; off <<= 1) {
        int t = (threadIdx.x >= off) ? sh[threadIdx.x - off] : 0;
        __syncthreads();
        sh[threadIdx.x] += t;
        __syncthreads();
    }
    if (i < NN) g_incl[i] = sh[threadIdx.x];
    if (threadIdx.x == SCAN_B - 1) g_part[blockIdx.x] = sh[SCAN_B - 1];
}

__global__ void k_scan2() {
    if (threadIdx.x == 0 && blockIdx.x == 0) {
        int run = 0;
        for (int b = 0; b < SCAN_NB; b++) {
            int t = g_part[b];
            g_part[b] = run;
            run += t;
        }
    }
}

__global__ void k_scan3() {
    int i = blockIdx.x * SCAN_B + threadIdx.x;
    if (i < NN) {
        int v = g_incl[i] + g_part[blockIdx.x];
        g_rowptr[i + 1] = v;
        g_cursor[i + 1] = v;
        if (i == 0) { g_rowptr[0] = 0; g_cursor[0] = 0; }
    }
}

__global__ void k_scatter(const int* __restrict__ dst) {
    int e = blockIdx.x * blockDim.x + threadIdx.x;
    if (e < NE) {
        int p = atomicAdd(&g_cursor[dst[e]], 1);
        g_eperm[p] = e;
    }
}

// ---------------- once: W -> pre-swizzled bf16 hi/lo images ----------------
__global__ void k_wconv(const float* __restrict__ Wq, const float* __restrict__ Wk,
                        const float* __restrict__ Wv, const float* __restrict__ Ws) {
    int img = blockIdx.x;  // 0..11
    int l = img >> 2, m = img & 3;
    const float* W =
        ((m == 0) ? Wq : (m == 1) ? Wk : (m == 2) ? Wv : Ws) + (long long)l * DD * DD;
    unsigned char* hi = g_WimgH + img * 32768;
    unsigned char* lo = g_WimgL + img * 32768;
    for (int i = threadIdx.x; i < DD * DD; i += blockDim.x) {
        int k = i >> 7, n = i & 127;  // B(k,n) = W[k][n]
        float w = W[k * DD + n];
        __nv_bfloat16 h = __float2bfloat16(w);
        float r = w - __bfloat162float(h);
        __nv_bfloat16 l2 = __float2bfloat16(r);
        int o = swz(k, n >> 3) + (n & 7) * 2;
        *(__nv_bfloat16*)(hi + o) = h;
        *(__nv_bfloat16*)(lo + o) = l2;
    }
}

// ---------------- per-layer: relation projection table (1000x128) ----------------
__global__ void k_erel(const float* __restrict__ rel, const float* __restrict__ We,
                       const float* __restrict__ be) {
    __shared__ float sr[DD];
    int r = blockIdx.x, j = threadIdx.x;
    sr[j] = rel[r * DD + j];
    __syncthreads();
    float acc = be[j];
#pragma unroll 8
    for (int i = 0; i < DD; i++) acc = fmaf(sr[i], We[i * DD + j], acc);
    g_Erel[r * DD + j] = acc;
}

// ---------------- mma.sync fused Q/K/V/Skip GEMM (split-bf16 fp32 accuracy) ------
// smem map
#define SM_BIAS 0          // 512 floats = 2048 B
#define SM_AHI 2048        // 32 KB each tile
#define SM_ALO (SM_AHI + 32768)
#define SM_BHI (SM_ALO + 32768)
#define SM_BLO (SM_BHI + 32768)
#define SM_TOT (SM_BLO + 32768)

__global__ void __launch_bounds__(256, 1)
k_qkvs_mma(const float* __restrict__ x, const float* __restrict__ bq,
           const float* __restrict__ bk, const float* __restrict__ bv,
           const float* __restrict__ bs, int layer) {
    extern __shared__ unsigned char smem[];
    uint32_t sb = smem_u32(smem);
    int t = threadIdx.x, w = t >> 5, lane = t & 31;
    int rowBase = blockIdx.x * 128;

    if (t < 128) {
        float* bsm = (float*)(smem + SM_BIAS);
        bsm[t] = bq[t];
        bsm[128 + t] = bk[t];
        bsm[256 + t] = bv[t];
        bsm[384 + t] = bs[t];
    }

    // A tile: fp32 x -> bf16 hi/lo, swizzled smem
#pragma unroll
    for (int it = 0; it < 16; it++) {
        int f4 = t + it * 256;  // 0..4095
        int r = f4 >> 5, c4 = (f4 & 31) << 2;
        float4 v = make_float4(0.f, 0.f, 0.f, 0.f);
        if (rowBase + r < NN) v = *(const float4*)&x[(long long)(rowBase + r) * 128 + c4];
        __nv_bfloat16 h0 = __float2bfloat16(v.x), h1 = __float2bfloat16(v.y),
                      h2 = __float2bfloat16(v.z), h3 = __float2bfloat16(v.w);
        __nv_bfloat16 l0 = __float2bfloat16(v.x - __bfloat162float(h0));
        __nv_bfloat16 l1 = __float2bfloat16(v.y - __bfloat162float(h1));
        __nv_bfloat16 l2 = __float2bfloat16(v.z - __bfloat162float(h2));
        __nv_bfloat16 l3 = __float2bfloat16(v.w - __bfloat162float(h3));
        uint2 hp, lp;
        hp.x = (uint32_t)__bfloat16_as_ushort(h0) | ((uint32_t)__bfloat16_as_ushort(h1) << 16);
        hp.y = (uint32_t)__bfloat16_as_ushort(h2) | ((uint32_t)__bfloat16_as_ushort(h3) << 16);
        lp.x = (uint32_t)__bfloat16_as_ushort(l0) | ((uint32_t)__bfloat16_as_ushort(l1) << 16);
        lp.y = (uint32_t)__bfloat16_as_ushort(l2) | ((uint32_t)__bfloat16_as_ushort(l3) << 16);
        int o = swz(r, c4 >> 3) + (c4 & 7) * 2;
        *(uint2*)(smem + SM_AHI + o) = hp;
        *(uint2*)(smem + SM_ALO + o) = lp;
    }

    // per-matrix loop: load B, mma, epilogue
    for (int mi = 0; mi < 4; mi++) {
        __syncthreads();  // previous matrix's mma done before overwriting B
        {
            const uint4* sh = (const uint4*)(g_WimgH + (layer * 4 + mi) * 32768);
            const uint4* sl = (const uint4*)(g_WimgL + (layer * 4 + mi) * 32768);
            uint4* ph = (uint4*)(smem + SM_BHI);
            uint4* pl = (uint4*)(smem + SM_BLO);
#pragma unroll
            for (int i = 0; i < 8; i++) {
                ph[t + i * 256] = sh[t + i * 256];
                pl[t + i * 256] = sl[t + i * 256];
            }
        }
        __syncthreads();

        float acc[16][4];
#pragma unroll
        for (int i = 0; i < 16; i++)
#pragma unroll
            for (int j = 0; j < 4; j++) acc[i][j] = 0.f;

        // A fragment addresses: row = w*16 + (lane&15), col group = ks*2 + (lane>>4)
        int arow = w * 16 + (lane & 15);
        // B (trans): mat = lane>>3; row = ks*16 + ((mat&1)<<3)+(lane&7); g = np*2+(mat>>1)
        int bmat = lane >> 3;
        int brow_in = ((bmat & 1) << 3) + (lane & 7);
        int bghalf = bmat >> 1;

#pragma unroll
        for (int ks = 0; ks < 8; ks++) {
            uint32_t ah0, ah1, ah2, ah3, al0, al1, al2, al3;
            uint32_t aaddr = sb + SM_AHI + swz(arow, ks * 2 + (lane >> 4));
            ldm_x4(ah0, ah1, ah2, ah3, aaddr);
            ldm_x4(al0, al1, al2, al3, aaddr + (SM_ALO - SM_AHI));
            int brow = ks * 16 + brow_in;
#pragma unroll
            for (int np = 0; np < 8; np++) {
                uint32_t bh0, bh1, bh2, bh3, bl0, bl1, bl2, bl3;
                uint32_t baddr = sb + SM_BHI + swz(brow, np * 2 + bghalf);
                ldm_x4t(bh0, bh1, bh2, bh3, baddr);
                ldm_x4t(bl0, bl1, bl2, bl3, baddr + (SM_BLO - SM_BHI));
                float* c0 = acc[np * 2];
                float* c1 = acc[np * 2 + 1];
                mma_bf16(c0, ah0, ah1, ah2, ah3, bh0, bh1);
                mma_bf16(c0, ah0, ah1, ah2, ah3, bl0, bl1);
                mma_bf16(c0, al0, al1, al2, al3, bh0, bh1);
                mma_bf16(c1, ah0, ah1, ah2, ah3, bh2, bh3);
                mma_bf16(c1, ah0, ah1, ah2, ah3, bl2, bl3);
                mma_bf16(c1, al0, al1, al2, al3, bh2, bh3);
            }
        }

        // epilogue
        float* outp = (mi == 0) ? g_Q : (mi == 1) ? g_K : (mi == 2) ? g_V : g_S;
        const float* bsm = (const float*)(smem + SM_BIAS) + mi * 128;
        int r0 = rowBase + w * 16 + (lane >> 2);
        int cb = (lane & 3) * 2;
#pragma unroll
        for (int nt = 0; nt < 16; nt++) {
            int col = nt * 8 + cb;
            float2 b2 = make_float2(bsm[col], bsm[col + 1]);
            if (r0 < NN) {
                float2 o0 = make_float2(acc[nt][0] + b2.x, acc[nt][1] + b2.y);
                *(float2*)&outp[(long long)r0 * 128 + col] = o0;
            }
            if (r0 + 8 < NN) {
                float2 o1 = make_float2(acc[nt][2] + b2.x, acc[nt][3] + b2.y);
                *(float2*)&outp[(long long)(r0 + 8) * 128 + col] = o1;
            }
        }
    }
}

// ---------------- fused attention / softmax / aggregate / LN / residual ----------------
__global__ void k_attn(float* __restrict__ x, const int* __restrict__ src,
                       const int* __restrict__ etype, const float* __restrict__ lng,
                       const float* __restrict__ lnb) {
    int n = blockIdx.x * (blockDim.x >> 5) + (threadIdx.x >> 5);
    int lane = threadIdx.x & 31;
    if (n >= NN) return;

    const float4* Q4 = (const float4*)g_Q;
    const float4* K4 = (const float4*)g_K;
    const float4* V4 = (const float4*)g_V;
    const float4* E4 = (const float4*)g_Erel;

    float4 q = Q4[n * 32 + lane];
    int beg = g_rowptr[n], end = g_rowptr[n + 1];

    float m = -3.4e38f, dsum = 0.f;
    float4 acc = make_float4(0.f, 0.f, 0.f, 0.f);

    for (int idx = beg; idx < end; idx++) {
        int e = g_eperm[idx];
        int s = src[e];
        int tt = etype[e];
        float4 ev = E4[tt * 32 + lane];
        float4 kv = K4[s * 32 + lane];
        float p = q.x * (kv.x + ev.x) + q.y * (kv.y + ev.y) + q.z * (kv.z + ev.z) +
                  q.w * (kv.w + ev.w);
        p += __shfl_xor_sync(0xffffffffu, p, 1);
        p += __shfl_xor_sync(0xffffffffu, p, 2);
        float alpha = p * 0.25f;  // 1/sqrt(16)
        float mn = fmaxf(m, alpha);
        float sc = __expf(m - mn);
        float wq = __expf(alpha - mn);
        dsum = dsum * sc + wq;
        float4 vv = V4[s * 32 + lane];
        acc.x = acc.x * sc + wq * (vv.x + ev.x);
        acc.y = acc.y * sc + wq * (vv.y + ev.y);
        acc.z = acc.z * sc + wq * (vv.z + ev.z);
        acc.w = acc.w * sc + wq * (vv.w + ev.w);
        m = mn;
    }

    float inv = (dsum > 0.f) ? (1.f / dsum) : 0.f;
    float4 sk = ((const float4*)g_S)[n * 32 + lane];
    float4 o = make_float4(acc.x * inv + sk.x, acc.y * inv + sk.y, acc.z * inv + sk.z,
                           acc.w * inv + sk.w);

    float sum = o.x + o.y + o.z + o.w;
#pragma unroll
    for (int off = 16; off; off >>= 1) sum += __shfl_xor_sync(0xffffffffu, sum, off);
    float mean = sum * (1.f / 128.f);
    float4 c = make_float4(o.x - mean, o.y - mean, o.z - mean, o.w - mean);
    float ss = c.x * c.x + c.y * c.y + c.z * c.z + c.w * c.w;
#pragma unroll
    for (int off = 16; off; off >>= 1) ss += __shfl_xor_sync(0xffffffffu, ss, off);
    float var = ss * (1.f / 128.f);
    float rstd = rsqrtf(var + 1e-5f);

    float4 g = ((const float4*)lng)[lane];
    float4 b = ((const float4*)lnb)[lane];
    float4 y;
    y.x = fmaxf(c.x * rstd * g.x + b.x, 0.f);
    y.y = fmaxf(c.y * rstd * g.y + b.y, 0.f);
    y.z = fmaxf(c.z * rstd * g.z + b.z, 0.f);
    y.w = fmaxf(c.w * rstd * g.w + b.w, 0.f);

    float4 xo = ((float4*)x)[n * 32 + lane];
    xo.x += y.x;
    xo.y += y.y;
    xo.z += y.z;
    xo.w += y.w;
    ((float4*)x)[n * 32 + lane] = xo;
}

// ---------------- graph embedding = mean over nodes ----------------
#define ROWS_PER 256
__global__ void k_colsum(const float* __restrict__ x) {
    int col = threadIdx.x;
    int rbeg = blockIdx.x * ROWS_PER;
    int rend = rbeg + ROWS_PER;
    if (rend > NN) rend = NN;
    float s = 0.f;
    for (int r = rbeg; r < rend; r++) s += x[(long long)r * DD + col];
    atomicAdd(&g_gsum[col], s);
}

__global__ void k_final(float* __restrict__ gout) {
    int c = threadIdx.x;
    if (c < DD) gout[c] = g_gsum[c] * (1.f / (float)NN);
}

// ---------------- launch ----------------
extern "C" void kernel_launch(void* const* d_in, const int* in_sizes, int n_in,
                              void* d_out, int out_size) {
    const int* node_ids = (const int*)d_in[0];
    const int* edge_index = (const int*)d_in[1];
    const int* edge_type = (const int*)d_in[2];
    const float* ent_emb = (const float*)d_in[3];
    const float* rel_emb = (const float*)d_in[4];
    const float* Wq = (const float*)d_in[5];
    const float* bq = (const float*)d_in[6];
    const float* Wk = (const float*)d_in[7];
    const float* bk = (const float*)d_in[8];
    const float* Wv = (const float*)d_in[9];
    const float* bv = (const float*)d_in[10];
    const float* We = (const float*)d_in[11];
    const float* be = (const float*)d_in[12];
    const float* Ws = (const float*)d_in[13];
    const float* bs = (const float*)d_in[14];
    const float* lng = (const float*)d_in[15];
    const float* lnb = (const float*)d_in[16];

    float* x = (float*)d_out;
    float* gout = (float*)d_out + (out_size - DD);

    const int* src = edge_index;
    const int* dst = edge_index + NE;

    cudaFuncSetAttribute(k_qkvs_mma, cudaFuncAttributeMaxDynamicSharedMemorySize, SM_TOT);

    // init + CSR build + W conversion (edges/W constant across layers)
    k_gather<<<(NN * 32 + 255) / 256, 256>>>(node_ids, ent_emb, x);
    k_zero<<<(NN + 255) / 256, 256>>>();
    k_count<<<(NE + 255) / 256, 256>>>(dst);
    k_scan1<<<SCAN_NB, SCAN_B>>>();
    k_scan2<<<1, 32>>>();
    k_scan3<<<SCAN_NB, SCAN_B>>>();
    k_scatter<<<(NE + 255) / 256, 256>>>(dst);
    k_wconv<<<12, 256>>>(Wq, Wk, Wv, Ws);

    for (int l = 0; l < NLAYER; l++) {
        long long wo = (long long)l * DD * DD;
        int bo = l * DD;
        k_erel<<<NREL, DD>>>(rel_emb, We + wo, be + bo);
        k_qkvs_mma<<<(NN + 127) / 128, 256, SM_TOT>>>(x, bq + bo, bk + bo, bv + bo, bs + bo, l);
        k_attn<<<(NN + 7) / 8, 256>>>(x, src, edge_type, lng + bo, lnb + bo);
    }

    k_colsum<<<(NN + ROWS_PER - 1) / ROWS_PER, DD>>>(x);
    k_final<<<1, DD>>>(gout);
}

// round 4
// speedup vs baseline: 1.6481x; 1.1868x over previous
#include <cuda_runtime.h>
#include <cuda_bf16.h>
#include <cstdint>

#define NN 100000
#define NE 600000
#define DD 128
#define NREL 1000
#define NLAYER 3
#define SCAN_B 1024
#define SCAN_NB ((NN + SCAN_B - 1) / SCAN_B)

// ---------------- scratch (static device globals; no allocs) ----------------
__device__ float g_Q[NN * DD];
__device__ float g_K[NN * DD];
__device__ float g_V[NN * DD];
__device__ float g_S[NN * DD];
__device__ float g_Erel[NREL * DD];
__device__ float g_gsum[DD];
__device__ int g_cnt[NN];
__device__ int g_incl[NN];
__device__ int g_part[SCAN_NB];
__device__ int g_rowptr[NN + 1];
__device__ int g_cursor[NN + 1];
__device__ int2 g_edge2[NE];  // dst-sorted (src, etype)
// pre-swizzled bf16 W images: 12 (3 layers x {Q,K,V,S}), hi and lo parts.
__device__ __align__(16) unsigned char g_WimgH[12 * 32768];
__device__ __align__(16) unsigned char g_WimgL[12 * 32768];

__device__ __forceinline__ uint32_t smem_u32(const void* p) {
    uint32_t a;
    asm("{ .reg .u64 t; cvta.to.shared.u64 t, %1; cvt.u32.u64 %0, t; }" : "=r"(a) : "l"(p));
    return a;
}
// swizzled byte offset inside a [128 x 128bf16] tile (256B rows)
__device__ __forceinline__ int swz(int row, int g16) {
    return row * 256 + ((g16 ^ (row & 7)) << 4);
}
__device__ __forceinline__ void ldm_x4(uint32_t& r0, uint32_t& r1, uint32_t& r2, uint32_t& r3,
                                       uint32_t addr) {
    asm volatile("ldmatrix.sync.aligned.m8n8.x4.shared.b16 {%0,%1,%2,%3}, [%4];"
                 : "=r"(r0), "=r"(r1), "=r"(r2), "=r"(r3)
                 : "r"(addr));
}
__device__ __forceinline__ void ldm_x4t(uint32_t& r0, uint32_t& r1, uint32_t& r2, uint32_t& r3,
                                        uint32_t addr) {
    asm volatile("ldmatrix.sync.aligned.m8n8.x4.trans.shared.b16 {%0,%1,%2,%3}, [%4];"
                 : "=r"(r0), "=r"(r1), "=r"(r2), "=r"(r3)
                 : "r"(addr));
}
__device__ __forceinline__ void mma_bf16(float* c, uint32_t a0, uint32_t a1, uint32_t a2,
                                         uint32_t a3, uint32_t b0, uint32_t b1) {
    asm volatile(
        "mma.sync.aligned.m16n8k16.row.col.f32.bf16.bf16.f32 "
        "{%0,%1,%2,%3}, {%4,%5,%6,%7}, {%8,%9}, {%0,%1,%2,%3};"
        : "+f"(c[0]), "+f"(c[1]), "+f"(c[2]), "+f"(c[3])
        : "r"(a0), "r"(a1), "r"(a2), "r"(a3), "r"(b0), "r"(b1));
}
__device__ __forceinline__ void cpa16(uint32_t dst, const void* src) {
    asm volatile("cp.async.cg.shared.global [%0], [%1], 16;" ::"r"(dst), "l"(src));
}
__device__ __forceinline__ void cpa_commit() {
    asm volatile("cp.async.commit_group;" ::: "memory");
}
template <int N>
__device__ __forceinline__ void cpa_wait() {
    asm volatile("cp.async.wait_group %0;" ::"n"(N) : "memory");
}

// ---------------- init: x = ent_emb[node_ids] ----------------
__global__ void k_gather(const int* __restrict__ ids, const float* __restrict__ emb,
                         float* __restrict__ x) {
    int i = blockIdx.x * blockDim.x + threadIdx.x;
    if (i >= NN * 32) return;
    int n = i >> 5, l = i & 31;
    ((float4*)x)[n * 32 + l] = ((const float4*)emb)[(long long)ids[n] * 32 + l];
}

__global__ void k_zero() {
    int i = blockIdx.x * blockDim.x + threadIdx.x;
    if (i < NN) g_cnt[i] = 0;
    if (i < DD) g_gsum[i] = 0.f;
}

// ---------------- CSR build (dst-sorted) ----------------
__global__ void k_count(const int* __restrict__ dst) {
    int e = blockIdx.x * blockDim.x + threadIdx.x;
    if (e < NE) atomicAdd(&g_cnt[dst[e]], 1);
}

__global__ void k_scan1() {
    __shared__ int sh[SCAN_B];
    int i = blockIdx.x * SCAN_B + threadIdx.x;
    int v = (i < NN) ? g_cnt[i] : 0;
    sh[threadIdx.x] = v;
    __syncthreads();
    for (int off = 1; off < SCAN_B; off <<= 1) {
        int t = (threadIdx.x >= off) ? sh[threadIdx.x - off] : 0;
        __syncthreads();
        sh[threadIdx.x] += t;
        __syncthreads();
    }
    if (i < NN) g_incl[i] = sh[threadIdx.x];
    if (threadIdx.x == SCAN_B - 1) g_part[blockIdx.x] = sh[SCAN_B - 1];
}

__global__ void k_scan2() {
    if (threadIdx.x == 0 && blockIdx.x == 0) {
        int run = 0;
        for (int b = 0; b < SCAN_NB; b++) {
            int t = g_part[b];
            g_part[b] = run;
            run += t;
        }
    }
}

__global__ void k_scan3() {
    int i = blockIdx.x * SCAN_B + threadIdx.x;
    if (i < NN) {
        int v = g_incl[i] + g_part[blockIdx.x];
        g_rowptr[i + 1] = v;
        g_cursor[i + 1] = v;
        if (i == 0) { g_rowptr[0] = 0; g_cursor[0] = 0; }
    }
}

__global__ void k_scatter(const int* __restrict__ src, const int* __restrict__ dst,
                          const int* __restrict__ etype) {
    int e = blockIdx.x * blockDim.x + threadIdx.x;
    if (e < NE) {
        int p = atomicAdd(&g_cursor[dst[e]], 1);
        g_edge2[p] = make_int2(src[e], etype[e]);
    }
}

// ---------------- once: W -> pre-swizzled bf16 hi/lo images ----------------
__global__ void k_wconv(const float* __restrict__ Wq, const float* __restrict__ Wk,
                        const float* __restrict__ Wv, const float* __restrict__ Ws) {
    int img = blockIdx.x;  // 0..11
    int l = img >> 2, m = img & 3;
    const float* W =
        ((m == 0) ? Wq : (m == 1) ? Wk : (m == 2) ? Wv : Ws) + (long long)l * DD * DD;
    unsigned char* hi = g_WimgH + img * 32768;
    unsigned char* lo = g_WimgL + img * 32768;
    for (int i = threadIdx.x; i < DD * DD; i += blockDim.x) {
        int k = i >> 7, n = i & 127;  // B(k,n) = W[k][n]
        float w = W[k * DD + n];
        __nv_bfloat16 h = __float2bfloat16(w);
        float r = w - __bfloat162float(h);
        __nv_bfloat16 l2 = __float2bfloat16(r);
        int o = swz(k, n >> 3) + (n & 7) * 2;
        *(__nv_bfloat16*)(hi + o) = h;
        *(__nv_bfloat16*)(lo + o) = l2;
    }
}

// ---------------- per-layer: relation projection table (1000x128) ----------------
__global__ void k_erel(const float* __restrict__ rel, const float* __restrict__ We,
                       const float* __restrict__ be) {
    __shared__ float sr[DD];
    int r = blockIdx.x, j = threadIdx.x;
    sr[j] = rel[r * DD + j];
    __syncthreads();
    float acc = be[j];
#pragma unroll 8
    for (int i = 0; i < DD; i++) acc = fmaf(sr[i], We[i * DD + j], acc);
    g_Erel[r * DD + j] = acc;
}

// ---------------- mma.sync fused Q/K/V/Skip GEMM (split-bf16 fp32 accuracy) ------
// smem map: bias 2KB | A hi/lo 64KB | B buf0 64KB | B buf1 64KB
#define SM_BIAS 0
#define SM_A 2048
#define SM_B0 (SM_A + 65536)
#define SM_B1 (SM_B0 + 65536)
#define SM_TOT (SM_B1 + 65536)

__device__ __forceinline__ void copyB_async(uint32_t sbdst, int img, int t) {
    const unsigned char* sh = g_WimgH + img * 32768;
    const unsigned char* sl = g_WimgL + img * 32768;
#pragma unroll
    for (int i = 0; i < 8; i++) {
        int o = (t + i * 256) * 16;
        cpa16(sbdst + o, sh + o);
        cpa16(sbdst + 32768 + o, sl + o);
    }
}

__global__ void __launch_bounds__(256, 1)
k_qkvs_mma(const float* __restrict__ x, const float* __restrict__ bq,
           const float* __restrict__ bk, const float* __restrict__ bv,
           const float* __restrict__ bs, int layer) {
    extern __shared__ unsigned char smem[];
    uint32_t sb = smem_u32(smem);
    int t = threadIdx.x, w = t >> 5, lane = t & 31;
    int wr = w & 3, wc = w >> 2;  // 4 row-groups x 2 col-groups
    int rowBase = blockIdx.x * 128;

    // prefetch B(0) while we convert A
    copyB_async(sb + SM_B0, layer * 4 + 0, t);
    cpa_commit();

    if (t < 128) {
        float* bsm = (float*)(smem + SM_BIAS);
        bsm[t] = bq[t];
        bsm[128 + t] = bk[t];
        bsm[256 + t] = bv[t];
        bsm[384 + t] = bs[t];
    }

    // A tile: fp32 x -> bf16 hi/lo, swizzled smem
#pragma unroll
    for (int it = 0; it < 16; it++) {
        int f4 = t + it * 256;  // 0..4095
        int r = f4 >> 5, c4 = (f4 & 31) << 2;
        float4 v = make_float4(0.f, 0.f, 0.f, 0.f);
        if (rowBase + r < NN) v = *(const float4*)&x[(long long)(rowBase + r) * 128 + c4];
        __nv_bfloat16 h0 = __float2bfloat16(v.x), h1 = __float2bfloat16(v.y),
                      h2 = __float2bfloat16(v.z), h3 = __float2bfloat16(v.w);
        __nv_bfloat16 l0 = __float2bfloat16(v.x - __bfloat162float(h0));
        __nv_bfloat16 l1 = __float2bfloat16(v.y - __bfloat162float(h1));
        __nv_bfloat16 l2 = __float2bfloat16(v.z - __bfloat162float(h2));
        __nv_bfloat16 l3 = __float2bfloat16(v.w - __bfloat162float(h3));
        uint2 hp, lp;
        hp.x = (uint32_t)__bfloat16_as_ushort(h0) | ((uint32_t)__bfloat16_as_ushort(h1) << 16);
        hp.y = (uint32_t)__bfloat16_as_ushort(h2) | ((uint32_t)__bfloat16_as_ushort(h3) << 16);
        lp.x = (uint32_t)__bfloat16_as_ushort(l0) | ((uint32_t)__bfloat16_as_ushort(l1) << 16);
        lp.y = (uint32_t)__bfloat16_as_ushort(l2) | ((uint32_t)__bfloat16_as_ushort(l3) << 16);
        int o = swz(r, c4 >> 3) + (c4 & 7) * 2;
        *(uint2*)(smem + SM_A + o) = hp;
        *(uint2*)(smem + SM_A + 32768 + o) = lp;
    }

    // per-matrix loop with double-buffered B
    for (int mi = 0; mi < 4; mi++) {
        uint32_t bcur = sb + ((mi & 1) ? SM_B1 : SM_B0);
        __syncthreads();  // all warps done reading the buffer we're about to refill
        if (mi < 3) {
            copyB_async(sb + (((mi + 1) & 1) ? SM_B1 : SM_B0), layer * 4 + mi + 1, t);
            cpa_commit();
            cpa_wait<1>();  // B(mi) complete
        } else {
            cpa_wait<0>();
        }
        __syncthreads();

        float acc[2][8][4];
#pragma unroll
        for (int a = 0; a < 2; a++)
#pragma unroll
            for (int i = 0; i < 8; i++)
#pragma unroll
                for (int j = 0; j < 4; j++) acc[a][i][j] = 0.f;

        int arow0 = wr * 32 + (lane & 15);
        int bmat = lane >> 3;
        int brow_in = ((bmat & 1) << 3) + (lane & 7);
        int bghalf = bmat >> 1;

#pragma unroll
        for (int ks = 0; ks < 8; ks++) {
            uint32_t ah[2][4], al[2][4];
            int ag = ks * 2 + (lane >> 4);
#pragma unroll
            for (int mt = 0; mt < 2; mt++) {
                uint32_t aaddr = sb + SM_A + swz(arow0 + mt * 16, ag);
                ldm_x4(ah[mt][0], ah[mt][1], ah[mt][2], ah[mt][3], aaddr);
                ldm_x4(al[mt][0], al[mt][1], al[mt][2], al[mt][3], aaddr + 32768);
            }
            int brow = ks * 16 + brow_in;
#pragma unroll
            for (int np = 0; np < 4; np++) {
                uint32_t bh0, bh1, bh2, bh3, bl0, bl1, bl2, bl3;
                uint32_t baddr = bcur + swz(brow, wc * 8 + np * 2 + bghalf);
                ldm_x4t(bh0, bh1, bh2, bh3, baddr);
                ldm_x4t(bl0, bl1, bl2, bl3, baddr + 32768);
#pragma unroll
                for (int mt = 0; mt < 2; mt++) {
                    float* c0 = acc[mt][np * 2];
                    float* c1 = acc[mt][np * 2 + 1];
                    mma_bf16(c0, ah[mt][0], ah[mt][1], ah[mt][2], ah[mt][3], bh0, bh1);
                    mma_bf16(c0, ah[mt][0], ah[mt][1], ah[mt][2], ah[mt][3], bl0, bl1);
                    mma_bf16(c0, al[mt][0], al[mt][1], al[mt][2], al[mt][3], bh0, bh1);
                    mma_bf16(c1, ah[mt][0], ah[mt][1], ah[mt][2], ah[mt][3], bh2, bh3);
                    mma_bf16(c1, ah[mt][0], ah[mt][1], ah[mt][2], ah[mt][3], bl2, bl3);
                    mma_bf16(c1, al[mt][0], al[mt][1], al[mt][2], al[mt][3], bh2, bh3);
                }
            }
        }

        // epilogue: warp covers rows wr*32..+32, cols wc*64..+64
        float* outp = (mi == 0) ? g_Q : (mi == 1) ? g_K : (mi == 2) ? g_V : g_S;
        const float* bsm = (const float*)(smem + SM_BIAS) + mi * 128;
        int cb = wc * 64 + (lane & 3) * 2;
#pragma unroll
        for (int mt = 0; mt < 2; mt++) {
            int r0 = rowBase + wr * 32 + mt * 16 + (lane >> 2);
#pragma unroll
            for (int nt = 0; nt < 8; nt++) {
                int col = cb + nt * 8;
                float2 b2 = make_float2(bsm[col], bsm[col + 1]);
                if (r0 < NN) {
                    float2 o0 =
                        make_float2(acc[mt][nt][0] + b2.x, acc[mt][nt][1] + b2.y);
                    *(float2*)&outp[(long long)r0 * 128 + col] = o0;
                }
                if (r0 + 8 < NN) {
                    float2 o1 =
                        make_float2(acc[mt][nt][2] + b2.x, acc[mt][nt][3] + b2.y);
                    *(float2*)&outp[(long long)(r0 + 8) * 128 + col] = o1;
                }
            }
        }
    }
}

// ---------------- fused attention / softmax / aggregate / LN / residual ----------------
__global__ void k_attn(float* __restrict__ x, const float* __restrict__ lng,
                       const float* __restrict__ lnb) {
    int n = blockIdx.x * (blockDim.x >> 5) + (threadIdx.x >> 5);
    int lane = threadIdx.x & 31;
    if (n >= NN) return;

    const float4* Q4 = (const float4*)g_Q;
    const float4* K4 = (const float4*)g_K;
    const float4* V4 = (const float4*)g_V;
    const float4* E4 = (const float4*)g_Erel;

    float4 q = Q4[n * 32 + lane];
    int beg = g_rowptr[n], end = g_rowptr[n + 1];

    float m = -3.4e38f, dsum = 0.f;
    float4 acc = make_float4(0.f, 0.f, 0.f, 0.f);

    int idx = beg;
    for (; idx + 1 < end; idx += 2) {
        int2 e0 = g_edge2[idx];
        int2 e1 = g_edge2[idx + 1];
        float4 kv0 = K4[e0.x * 32 + lane];
        float4 kv1 = K4[e1.x * 32 + lane];
        float4 ev0 = E4[e0.y * 32 + lane];
        float4 ev1 = E4[e1.y * 32 + lane];
        float4 vv0 = V4[e0.x * 32 + lane];
        float4 vv1 = V4[e1.x * 32 + lane];
        float p0 = q.x * (kv0.x + ev0.x) + q.y * (kv0.y + ev0.y) + q.z * (kv0.z + ev0.z) +
                   q.w * (kv0.w + ev0.w);
        float p1 = q.x * (kv1.x + ev1.x) + q.y * (kv1.y + ev1.y) + q.z * (kv1.z + ev1.z) +
                   q.w * (kv1.w + ev1.w);
        p0 += __shfl_xor_sync(0xffffffffu, p0, 1);
        p1 += __shfl_xor_sync(0xffffffffu, p1, 1);
        p0 += __shfl_xor_sync(0xffffffffu, p0, 2);
        p1 += __shfl_xor_sync(0xffffffffu, p1, 2);
        float a0 = p0 * 0.25f, a1 = p1 * 0.25f;
        float mn = fmaxf(m, fmaxf(a0, a1));
        float sc = __expf(m - mn);
        float w0 = __expf(a0 - mn);
        float w1 = __expf(a1 - mn);
        dsum = dsum * sc + w0 + w1;
        acc.x = acc.x * sc + w0 * (vv0.x + ev0.x) + w1 * (vv1.x + ev1.x);
        acc.y = acc.y * sc + w0 * (vv0.y + ev0.y) + w1 * (vv1.y + ev1.y);
        acc.z = acc.z * sc + w0 * (vv0.z + ev0.z) + w1 * (vv1.z + ev1.z);
        acc.w = acc.w * sc + w0 * (vv0.w + ev0.w) + w1 * (vv1.w + ev1.w);
        m = mn;
    }
    if (idx < end) {
        int2 e0 = g_edge2[idx];
        float4 kv0 = K4[e0.x * 32 + lane];
        float4 ev0 = E4[e0.y * 32 + lane];
        float4 vv0 = V4[e0.x * 32 + lane];
        float p0 = q.x * (kv0.x + ev0.x) + q.y * (kv0.y + ev0.y) + q.z * (kv0.z + ev0.z) +
                   q.w * (kv0.w + ev0.w);
        p0 += __shfl_xor_sync(0xffffffffu, p0, 1);
        p0 += __shfl_xor_sync(0xffffffffu, p0, 2);
        float a0 = p0 * 0.25f;
        float mn = fmaxf(m, a0);
        float sc = __expf(m - mn);
        float w0 = __expf(a0 - mn);
        dsum = dsum * sc + w0;
        acc.x = acc.x * sc + w0 * (vv0.x + ev0.x);
        acc.y = acc.y * sc + w0 * (vv0.y + ev0.y);
        acc.z = acc.z * sc + w0 * (vv0.z + ev0.z);
        acc.w = acc.w * sc + w0 * (vv0.w + ev0.w);
        m = mn;
    }

    float inv = (dsum > 0.f) ? (1.f / dsum) : 0.f;
    float4 sk = ((const float4*)g_S)[n * 32 + lane];
    float4 o = make_float4(acc.x * inv + sk.x, acc.y * inv + sk.y, acc.z * inv + sk.z,
                           acc.w * inv + sk.w);

    float sum = o.x + o.y + o.z + o.w;
#pragma unroll
    for (int off = 16; off; off >>= 1) sum += __shfl_xor_sync(0xffffffffu, sum, off);
    float mean = sum * (1.f / 128.f);
    float4 c = make_float4(o.x - mean, o.y - mean, o.z - mean, o.w - mean);
    float ss = c.x * c.x + c.y * c.y + c.z * c.z + c.w * c.w;
#pragma unroll
    for (int off = 16; off; off >>= 1) ss += __shfl_xor_sync(0xffffffffu, ss, off);
    float var = ss * (1.f / 128.f);
    float rstd = rsqrtf(var + 1e-5f);

    float4 g = ((const float4*)lng)[lane];
    float4 b = ((const float4*)lnb)[lane];
    float4 y;
    y.x = fmaxf(c.x * rstd * g.x + b.x, 0.f);
    y.y = fmaxf(c.y * rstd * g.y + b.y, 0.f);
    y.z = fmaxf(c.z * rstd * g.z + b.z, 0.f);
    y.w = fmaxf(c.w * rstd * g.w + b.w, 0.f);

    float4 xo = ((float4*)x)[n * 32 + lane];
    xo.x += y.x;
    xo.y += y.y;
    xo.z += y.z;
    xo.w += y.w;
    ((float4*)x)[n * 32 + lane] = xo;
}

// ---------------- graph embedding = mean over nodes ----------------
#define ROWS_PER 256
__global__ void k_colsum(const float* __restrict__ x) {
    int col = threadIdx.x;
    int rbeg = blockIdx.x * ROWS_PER;
    int rend = rbeg + ROWS_PER;
    if (rend > NN) rend = NN;
    float s = 0.f;
    for (int r = rbeg; r < rend; r++) s += x[(long long)r * DD + col];
    atomicAdd(&g_gsum[col], s);
}

__global__ void k_final(float* __restrict__ gout) {
    int c = threadIdx.x;
    if (c < DD) gout[c] = g_gsum[c] * (1.f / (float)NN);
}

// ---------------- launch ----------------
extern "C" void kernel_launch(void* const* d_in, const int* in_sizes, int n_in,
                              void* d_out, int out_size) {
    const int* node_ids = (const int*)d_in[0];
    const int* edge_index = (const int*)d_in[1];
    const int* edge_type = (const int*)d_in[2];
    const float* ent_emb = (const float*)d_in[3];
    const float* rel_emb = (const float*)d_in[4];
    const float* Wq = (const float*)d_in[5];
    const float* bq = (const float*)d_in[6];
    const float* Wk = (const float*)d_in[7];
    const float* bk = (const float*)d_in[8];
    const float* Wv = (const float*)d_in[9];
    const float* bv = (const float*)d_in[10];
    const float* We = (const float*)d_in[11];
    const float* be = (const float*)d_in[12];
    const float* Ws = (const float*)d_in[13];
    const float* bs = (const float*)d_in[14];
    const float* lng = (const float*)d_in[15];
    const float* lnb = (const float*)d_in[16];

    float* x = (float*)d_out;
    float* gout = (float*)d_out + (out_size - DD);

    const int* src = edge_index;
    const int* dst = edge_index + NE;

    cudaFuncSetAttribute(k_qkvs_mma, cudaFuncAttributeMaxDynamicSharedMemorySize, SM_TOT);

    // init + CSR build + W conversion (edges/W constant across layers)
    k_gather<<<(NN * 32 + 255) / 256, 256>>>(node_ids, ent_emb, x);
    k_zero<<<(NN + 255) / 256, 256>>>();
    k_count<<<(NE + 255) / 256, 256>>>(dst);
    k_scan1<<<SCAN_NB, SCAN_B>>>();
    k_scan2<<<1, 32>>>();
    k_scan3<<<SCAN_NB, SCAN_B>>>();
    k_scatter<<<(NE + 255) / 256, 256>>>(src, dst, edge_type);
    k_wconv<<<12, 256>>>(Wq, Wk, Wv, Ws);

    for (int l = 0; l < NLAYER; l++) {
        long long wo = (long long)l * DD * DD;
        int bo = l * DD;
        k_erel<<<NREL, DD>>>(rel_emb, We + wo, be + bo);
        k_qkvs_mma<<<(NN + 127) / 128, 256, SM_TOT>>>(x, bq + bo, bk + bo, bv + bo, bs + bo, l);
        k_attn<<<(NN + 7) / 8, 256>>>(x, lng + bo, lnb + bo);
    }

    k_colsum<<<(NN + ROWS_PER - 1) / ROWS_PER, DD>>>(x);
    k_final<<<1, DD>>>(gout);
}

// round 5
// speedup vs baseline: 1.6630x; 1.0090x over previous
#include <cuda_runtime.h>
#include <cuda_bf16.h>
#include <cstdint>

#define NN 100000
#define NE 600000
#define DD 128
#define NREL 1000
#define NLAYER 3
#define SCAN_B 1024
#define SCAN_NB ((NN + SCAN_B - 1) / SCAN_B)

// ---------------- scratch (static device globals; no allocs) ----------------
__device__ float g_Q[NN * DD];
__device__ float g_KV[NN * 256];  // per node: K row [0..127] then V row [128..255]
__device__ float g_S[NN * DD];
__device__ float g_Erel[NREL * DD];
__device__ float g_gsum[DD];
__device__ int g_cnt[NN];
__device__ int g_incl[NN];
__device__ int g_part[SCAN_NB];
__device__ int g_rowptr[NN + 1];
__device__ int g_cursor[NN + 1];
__device__ int2 g_edge2[NE];  // dst-sorted (src, etype)
__device__ __align__(16) unsigned char g_WimgH[12 * 32768];
__device__ __align__(16) unsigned char g_WimgL[12 * 32768];

__device__ __forceinline__ uint32_t smem_u32(const void* p) {
    uint32_t a;
    asm("{ .reg .u64 t; cvta.to.shared.u64 t, %1; cvt.u32.u64 %0, t; }" : "=r"(a) : "l"(p));
    return a;
}
__device__ __forceinline__ int swz(int row, int g16) {
    return row * 256 + ((g16 ^ (row & 7)) << 4);
}
__device__ __forceinline__ void ldm_x4(uint32_t& r0, uint32_t& r1, uint32_t& r2, uint32_t& r3,
                                       uint32_t addr) {
    asm volatile("ldmatrix.sync.aligned.m8n8.x4.shared.b16 {%0,%1,%2,%3}, [%4];"
                 : "=r"(r0), "=r"(r1), "=r"(r2), "=r"(r3)
                 : "r"(addr));
}
__device__ __forceinline__ void ldm_x4t(uint32_t& r0, uint32_t& r1, uint32_t& r2, uint32_t& r3,
                                        uint32_t addr) {
    asm volatile("ldmatrix.sync.aligned.m8n8.x4.trans.shared.b16 {%0,%1,%2,%3}, [%4];"
                 : "=r"(r0), "=r"(r1), "=r"(r2), "=r"(r3)
                 : "r"(addr));
}
__device__ __forceinline__ void mma_bf16(float* c, const uint32_t* a, uint32_t b0,
                                         uint32_t b1) {
    asm volatile(
        "mma.sync.aligned.m16n8k16.row.col.f32.bf16.bf16.f32 "
        "{%0,%1,%2,%3}, {%4,%5,%6,%7}, {%8,%9}, {%0,%1,%2,%3};"
        : "+f"(c[0]), "+f"(c[1]), "+f"(c[2]), "+f"(c[3])
        : "r"(a[0]), "r"(a[1]), "r"(a[2]), "r"(a[3]), "r"(b0), "r"(b1));
}
__device__ __forceinline__ void cpa16(uint32_t dst, const void* src) {
    asm volatile("cp.async.cg.shared.global [%0], [%1], 16;" ::"r"(dst), "l"(src));
}
__device__ __forceinline__ void cpa_commit() {
    asm volatile("cp.async.commit_group;" ::: "memory");
}
template <int N>
__device__ __forceinline__ void cpa_wait() {
    asm volatile("cp.async.wait_group %0;" ::"n"(N) : "memory");
}

// ---------------- init: x = ent_emb[node_ids] ----------------
__global__ void k_gather(const int* __restrict__ ids, const float* __restrict__ emb,
                         float* __restrict__ x) {
    int i = blockIdx.x * blockDim.x + threadIdx.x;
    if (i >= NN * 32) return;
    int n = i >> 5, l = i & 31;
    ((float4*)x)[n * 32 + l] = ((const float4*)emb)[(long long)ids[n] * 32 + l];
}

__global__ void k_zero() {
    int i = blockIdx.x * blockDim.x + threadIdx.x;
    if (i < NN) g_cnt[i] = 0;
    if (i < DD) g_gsum[i] = 0.f;
}

// ---------------- CSR build (dst-sorted) ----------------
__global__ void k_count(const int* __restrict__ dst) {
    int e = blockIdx.x * blockDim.x + threadIdx.x;
    if (e < NE) atomicAdd(&g_cnt[dst[e]], 1);
}

__global__ void k_scan1() {
    __shared__ int sh[SCAN_B];
    int i = blockIdx.x * SCAN_B + threadIdx.x;
    int v = (i < NN) ? g_cnt[i] : 0;
    sh[threadIdx.x] = v;
    __syncthreads();
    for (int off = 1; off < SCAN_B; off <<= 1) {
        int t = (threadIdx.x >= off) ? sh[threadIdx.x - off] : 0;
        __syncthreads();
        sh[threadIdx.x] += t;
        __syncthreads();
    }
    if (i < NN) g_incl[i] = sh[threadIdx.x];
    if (threadIdx.x == SCAN_B - 1) g_part[blockIdx.x] = sh[SCAN_B - 1];
}

__global__ void k_scan2() {
    if (threadIdx.x == 0 && blockIdx.x == 0) {
        int run = 0;
        for (int b = 0; b < SCAN_NB; b++) {
            int t = g_part[b];
            g_part[b] = run;
            run += t;
        }
    }
}

__global__ void k_scan3() {
    int i = blockIdx.x * SCAN_B + threadIdx.x;
    if (i < NN) {
        int v = g_incl[i] + g_part[blockIdx.x];
        g_rowptr[i + 1] = v;
        g_cursor[i + 1] = v;
        if (i == 0) { g_rowptr[0] = 0; g_cursor[0] = 0; }
    }
}

__global__ void k_scatter(const int* __restrict__ src, const int* __restrict__ dst,
                          const int* __restrict__ etype) {
    int e = blockIdx.x * blockDim.x + threadIdx.x;
    if (e < NE) {
        int p = atomicAdd(&g_cursor[dst[e]], 1);
        g_edge2[p] = make_int2(src[e], etype[e]);
    }
}

// ---------------- once: W -> pre-swizzled bf16 hi/lo images ----------------
__global__ void k_wconv(const float* __restrict__ Wq, const float* __restrict__ Wk,
                        const float* __restrict__ Wv, const float* __restrict__ Ws) {
    int img = blockIdx.x;  // 0..11
    int l = img >> 2, m = img & 3;
    const float* W =
        ((m == 0) ? Wq : (m == 1) ? Wk : (m == 2) ? Wv : Ws) + (long long)l * DD * DD;
    unsigned char* hi = g_WimgH + img * 32768;
    unsigned char* lo = g_WimgL + img * 32768;
    for (int i = threadIdx.x; i < DD * DD; i += blockDim.x) {
        int k = i >> 7, n = i & 127;  // B(k,n) = W[k][n]
        float w = W[k * DD + n];
        __nv_bfloat16 h = __float2bfloat16(w);
        float r = w - __bfloat162float(h);
        __nv_bfloat16 l2 = __float2bfloat16(r);
        int o = swz(k, n >> 3) + (n & 7) * 2;
        *(__nv_bfloat16*)(hi + o) = h;
        *(__nv_bfloat16*)(lo + o) = l2;
    }
}

// ---------------- per-layer: relation projection table (1000x128) ----------------
__global__ void k_erel(const float* __restrict__ rel, const float* __restrict__ We,
                       const float* __restrict__ be) {
    __shared__ float sr[DD];
    int r = blockIdx.x, j = threadIdx.x;
    sr[j] = rel[r * DD + j];
    __syncthreads();
    float acc = be[j];
#pragma unroll 8
    for (int i = 0; i < DD; i++) acc = fmaf(sr[i], We[i * DD + j], acc);
    g_Erel[r * DD + j] = acc;
}

// ---------------- mma.sync fused Q/K/V/Skip GEMM (split-bf16 fp32 accuracy) ------
#define SM_BIAS 0
#define SM_A 2048
#define SM_B0 (SM_A + 65536)
#define SM_B1 (SM_B0 + 65536)
#define SM_TOT (SM_B1 + 65536)

__device__ __forceinline__ void copyB_async(uint32_t sbdst, int img, int t) {
    const unsigned char* sh = g_WimgH + img * 32768;
    const unsigned char* sl = g_WimgL + img * 32768;
#pragma unroll
    for (int i = 0; i < 8; i++) {
        int o = (t + i * 256) * 16;
        cpa16(sbdst + o, sh + o);
        cpa16(sbdst + 32768 + o, sl + o);
    }
}

__global__ void __launch_bounds__(256, 1)
k_qkvs_mma(const float* __restrict__ x, const float* __restrict__ bq,
           const float* __restrict__ bk, const float* __restrict__ bv,
           const float* __restrict__ bs, int layer) {
    extern __shared__ unsigned char smem[];
    uint32_t sb = smem_u32(smem);
    int t = threadIdx.x, w = t >> 5, lane = t & 31;
    int wr = w & 3, wc = w >> 2;  // 4 row-groups x 2 col-groups
    int rowBase = blockIdx.x * 128;

    copyB_async(sb + SM_B0, layer * 4 + 0, t);
    cpa_commit();

    if (t < 128) {
        float* bsm = (float*)(smem + SM_BIAS);
        bsm[t] = bq[t];
        bsm[128 + t] = bk[t];
        bsm[256 + t] = bv[t];
        bsm[384 + t] = bs[t];
    }

    // A tile: fp32 x -> bf16 hi/lo, swizzled smem
#pragma unroll
    for (int it = 0; it < 16; it++) {
        int f4 = t + it * 256;
        int r = f4 >> 5, c4 = (f4 & 31) << 2;
        float4 v = make_float4(0.f, 0.f, 0.f, 0.f);
        if (rowBase + r < NN) v = *(const float4*)&x[(long long)(rowBase + r) * 128 + c4];
        __nv_bfloat16 h0 = __float2bfloat16(v.x), h1 = __float2bfloat16(v.y),
                      h2 = __float2bfloat16(v.z), h3 = __float2bfloat16(v.w);
        __nv_bfloat16 l0 = __float2bfloat16(v.x - __bfloat162float(h0));
        __nv_bfloat16 l1 = __float2bfloat16(v.y - __bfloat162float(h1));
        __nv_bfloat16 l2 = __float2bfloat16(v.z - __bfloat162float(h2));
        __nv_bfloat16 l3 = __float2bfloat16(v.w - __bfloat162float(h3));
        uint2 hp, lp;
        hp.x = (uint32_t)__bfloat16_as_ushort(h0) | ((uint32_t)__bfloat16_as_ushort(h1) << 16);
        hp.y = (uint32_t)__bfloat16_as_ushort(h2) | ((uint32_t)__bfloat16_as_ushort(h3) << 16);
        lp.x = (uint32_t)__bfloat16_as_ushort(l0) | ((uint32_t)__bfloat16_as_ushort(l1) << 16);
        lp.y = (uint32_t)__bfloat16_as_ushort(l2) | ((uint32_t)__bfloat16_as_ushort(l3) << 16);
        int o = swz(r, c4 >> 3) + (c4 & 7) * 2;
        *(uint2*)(smem + SM_A + o) = hp;
        *(uint2*)(smem + SM_A + 32768 + o) = lp;
    }

    for (int mi = 0; mi < 4; mi++) {
        uint32_t bcur = sb + ((mi & 1) ? SM_B1 : SM_B0);
        __syncthreads();
        if (mi < 3) {
            copyB_async(sb + (((mi + 1) & 1) ? SM_B1 : SM_B0), layer * 4 + mi + 1, t);
            cpa_commit();
            cpa_wait<1>();
        } else {
            cpa_wait<0>();
        }
        __syncthreads();

        float acc[2][8][4];
#pragma unroll
        for (int a = 0; a < 2; a++)
#pragma unroll
            for (int i = 0; i < 8; i++)
#pragma unroll
                for (int j = 0; j < 4; j++) acc[a][i][j] = 0.f;

        int arow0 = wr * 32 + (lane & 15);
        int bmat = lane >> 3;
        int brow_in = ((bmat & 1) << 3) + (lane & 7);
        int bghalf = bmat >> 1;

#pragma unroll
        for (int ks = 0; ks < 8; ks++) {
            uint32_t ah[2][4], al[2][4];
            int ag = ks * 2 + (lane >> 4);
#pragma unroll
            for (int mt = 0; mt < 2; mt++) {
                uint32_t aaddr = sb + SM_A + swz(arow0 + mt * 16, ag);
                ldm_x4(ah[mt][0], ah[mt][1], ah[mt][2], ah[mt][3], aaddr);
                ldm_x4(al[mt][0], al[mt][1], al[mt][2], al[mt][3], aaddr + 32768);
            }
            int brow = ks * 16 + brow_in;
            uint32_t bh[4][4], bl[4][4];
#pragma unroll
            for (int np = 0; np < 4; np++) {
                uint32_t baddr = bcur + swz(brow, wc * 8 + np * 2 + bghalf);
                ldm_x4t(bh[np][0], bh[np][1], bh[np][2], bh[np][3], baddr);
                ldm_x4t(bl[np][0], bl[np][1], bl[np][2], bl[np][3], baddr + 32768);
            }
            // term 1: Ah * Bh  (16 independent accumulators back-to-back)
#pragma unroll
            for (int np = 0; np < 4; np++)
#pragma unroll
                for (int mt = 0; mt < 2; mt++) {
                    mma_bf16(acc[mt][np * 2], ah[mt], bh[np][0], bh[np][1]);
                    mma_bf16(acc[mt][np * 2 + 1], ah[mt], bh[np][2], bh[np][3]);
                }
            // term 2: Ah * Bl
#pragma unroll
            for (int np = 0; np < 4; np++)
#pragma unroll
                for (int mt = 0; mt < 2; mt++) {
                    mma_bf16(acc[mt][np * 2], ah[mt], bl[np][0], bl[np][1]);
                    mma_bf16(acc[mt][np * 2 + 1], ah[mt], bl[np][2], bl[np][3]);
                }
            // term 3: Al * Bh
#pragma unroll
            for (int np = 0; np < 4; np++)
#pragma unroll
                for (int mt = 0; mt < 2; mt++) {
                    mma_bf16(acc[mt][np * 2], al[mt], bh[np][0], bh[np][1]);
                    mma_bf16(acc[mt][np * 2 + 1], al[mt], bh[np][2], bh[np][3]);
                }
        }

        // epilogue; K/V interleave into g_KV (K at +0, V at +128; row stride 256)
        float* outp;
        int rstride;
        if (mi == 0) { outp = g_Q; rstride = 128; }
        else if (mi == 1) { outp = g_KV; rstride = 256; }
        else if (mi == 2) { outp = g_KV + 128; rstride = 256; }
        else { outp = g_S; rstride = 128; }
        const float* bsm = (const float*)(smem + SM_BIAS) + mi * 128;
        int cb = wc * 64 + (lane & 3) * 2;
#pragma unroll
        for (int mt = 0; mt < 2; mt++) {
            int r0 = rowBase + wr * 32 + mt * 16 + (lane >> 2);
#pragma unroll
            for (int nt = 0; nt < 8; nt++) {
                int col = cb + nt * 8;
                float2 b2 = make_float2(bsm[col], bsm[col + 1]);
                if (r0 < NN) {
                    float2 o0 = make_float2(acc[mt][nt][0] + b2.x, acc[mt][nt][1] + b2.y);
                    *(float2*)&outp[(long long)r0 * rstride + col] = o0;
                }
                if (r0 + 8 < NN) {
                    float2 o1 = make_float2(acc[mt][nt][2] + b2.x, acc[mt][nt][3] + b2.y);
                    *(float2*)&outp[(long long)(r0 + 8) * rstride + col] = o1;
                }
            }
        }
    }
}

// ---------------- fused attention / softmax / aggregate / LN / residual ----------------
// NN = 100000 = 12500 blocks * 8 warps exactly (no early-exit warps).
__global__ void k_attn(float* __restrict__ x, const float* __restrict__ lng,
                       const float* __restrict__ lnb, int last) {
    __shared__ float sums[DD];
    int n = blockIdx.x * (blockDim.x >> 5) + (threadIdx.x >> 5);
    int lane = threadIdx.x & 31;

    const float4* Q4 = (const float4*)g_Q;
    const float4* KV4 = (const float4*)g_KV;
    const float4* E4 = (const float4*)g_Erel;

    float4 q = Q4[n * 32 + lane];
    int beg = g_rowptr[n], end = g_rowptr[n + 1];

    float m = -3.4e38f, dsum = 0.f;
    float4 acc = make_float4(0.f, 0.f, 0.f, 0.f);

    int idx = beg;
#define EDGE_LOAD(i, e)                                   \
    float4 kv##i = KV4[(e).x * 64 + lane];                \
    float4 vv##i = KV4[(e).x * 64 + 32 + lane];           \
    float4 ev##i = E4[(e).y * 32 + lane];
#define EDGE_DOT(i)                                                              \
    float p##i = q.x * (kv##i.x + ev##i.x) + q.y * (kv##i.y + ev##i.y) +         \
                 q.z * (kv##i.z + ev##i.z) + q.w * (kv##i.w + ev##i.w);          \
    p##i += __shfl_xor_sync(0xffffffffu, p##i, 1);                               \
    p##i += __shfl_xor_sync(0xffffffffu, p##i, 2);                               \
    float a##i = p##i * 0.25f;
#define EDGE_ACC(i)                                                \
    acc.x += w##i * (vv##i.x + ev##i.x);                           \
    acc.y += w##i * (vv##i.y + ev##i.y);                           \
    acc.z += w##i * (vv##i.z + ev##i.z);                           \
    acc.w += w##i * (vv##i.w + ev##i.w);

    for (; idx + 3 < end; idx += 4) {
        int2 e0 = g_edge2[idx];
        int2 e1 = g_edge2[idx + 1];
        int2 e2 = g_edge2[idx + 2];
        int2 e3 = g_edge2[idx + 3];
        EDGE_LOAD(0, e0) EDGE_LOAD(1, e1) EDGE_LOAD(2, e2) EDGE_LOAD(3, e3)
        EDGE_DOT(0) EDGE_DOT(1) EDGE_DOT(2) EDGE_DOT(3)
        float mn = fmaxf(fmaxf(m, fmaxf(a0, a1)), fmaxf(a2, a3));
        float sc = __expf(m - mn);
        float w0 = __expf(a0 - mn), w1 = __expf(a1 - mn);
        float w2 = __expf(a2 - mn), w3 = __expf(a3 - mn);
        dsum = dsum * sc + w0 + w1 + w2 + w3;
        acc.x *= sc; acc.y *= sc; acc.z *= sc; acc.w *= sc;
        EDGE_ACC(0) EDGE_ACC(1) EDGE_ACC(2) EDGE_ACC(3)
        m = mn;
    }
    for (; idx < end; idx++) {
        int2 e0 = g_edge2[idx];
        EDGE_LOAD(0, e0)
        EDGE_DOT(0)
        float mn = fmaxf(m, a0);
        float sc = __expf(m - mn);
        float w0 = __expf(a0 - mn);
        dsum = dsum * sc + w0;
        acc.x *= sc; acc.y *= sc; acc.z *= sc; acc.w *= sc;
        EDGE_ACC(0)
        m = mn;
    }

    float inv = (dsum > 0.f) ? (1.f / dsum) : 0.f;
    float4 sk = ((const float4*)g_S)[n * 32 + lane];
    float4 o = make_float4(acc.x * inv + sk.x, acc.y * inv + sk.y, acc.z * inv + sk.z,
                           acc.w * inv + sk.w);

    float sum = o.x + o.y + o.z + o.w;
#pragma unroll
    for (int off = 16; off; off >>= 1) sum += __shfl_xor_sync(0xffffffffu, sum, off);
    float mean = sum * (1.f / 128.f);
    float4 c = make_float4(o.x - mean, o.y - mean, o.z - mean, o.w - mean);
    float ss = c.x * c.x + c.y * c.y + c.z * c.z + c.w * c.w;
#pragma unroll
    for (int off = 16; off; off >>= 1) ss += __shfl_xor_sync(0xffffffffu, ss, off);
    float var = ss * (1.f / 128.f);
    float rstd = rsqrtf(var + 1e-5f);

    float4 g = ((const float4*)lng)[lane];
    float4 b = ((const float4*)lnb)[lane];
    float4 y;
    y.x = fmaxf(c.x * rstd * g.x + b.x, 0.f);
    y.y = fmaxf(c.y * rstd * g.y + b.y, 0.f);
    y.z = fmaxf(c.z * rstd * g.z + b.z, 0.f);
    y.w = fmaxf(c.w * rstd * g.w + b.w, 0.f);

    float4 xo = ((float4*)x)[n * 32 + lane];
    xo.x += y.x;
    xo.y += y.y;
    xo.z += y.z;
    xo.w += y.w;
    ((float4*)x)[n * 32 + lane] = xo;

    if (last) {  // fold graph-mean column sums into last layer
        if (threadIdx.x < DD) sums[threadIdx.x] = 0.f;
        __syncthreads();
        atomicAdd(&sums[lane * 4 + 0], xo.x);
        atomicAdd(&sums[lane * 4 + 1], xo.y);
        atomicAdd(&sums[lane * 4 + 2], xo.z);
        atomicAdd(&sums[lane * 4 + 3], xo.w);
        __syncthreads();
        if (threadIdx.x < DD) atomicAdd(&g_gsum[threadIdx.x], sums[threadIdx.x]);
    }
}

__global__ void k_final(float* __restrict__ gout) {
    int c = threadIdx.x;
    if (c < DD) gout[c] = g_gsum[c] * (1.f / (float)NN);
}

// ---------------- launch ----------------
extern "C" void kernel_launch(void* const* d_in, const int* in_sizes, int n_in,
                              void* d_out, int out_size) {
    const int* node_ids = (const int*)d_in[0];
    const int* edge_index = (const int*)d_in[1];
    const int* edge_type = (const int*)d_in[2];
    const float* ent_emb = (const float*)d_in[3];
    const float* rel_emb = (const float*)d_in[4];
    const float* Wq = (const float*)d_in[5];
    const float* bq = (const float*)d_in[6];
    const float* Wk = (const float*)d_in[7];
    const float* bk = (const float*)d_in[8];
    const float* Wv = (const float*)d_in[9];
    const float* bv = (const float*)d_in[10];
    const float* We = (const float*)d_in[11];
    const float* be = (const float*)d_in[12];
    const float* Ws = (const float*)d_in[13];
    const float* bs = (const float*)d_in[14];
    const float* lng = (const float*)d_in[15];
    const float* lnb = (const float*)d_in[16];

    float* x = (float*)d_out;
    float* gout = (float*)d_out + (out_size - DD);

    const int* src = edge_index;
    const int* dst = edge_index + NE;

    cudaFuncSetAttribute(k_qkvs_mma, cudaFuncAttributeMaxDynamicSharedMemorySize, SM_TOT);

    k_gather<<<(NN * 32 + 255) / 256, 256>>>(node_ids, ent_emb, x);
    k_zero<<<(NN + 255) / 256, 256>>>();
    k_count<<<(NE + 255) / 256, 256>>>(dst);
    k_scan1<<<SCAN_NB, SCAN_B>>>();
    k_scan2<<<1, 32>>>();
    k_scan3<<<SCAN_NB, SCAN_B>>>();
    k_scatter<<<(NE + 255) / 256, 256>>>(src, dst, edge_type);
    k_wconv<<<12, 256>>>(Wq, Wk, Wv, Ws);

    for (int l = 0; l < NLAYER; l++) {
        long long wo = (long long)l * DD * DD;
        int bo = l * DD;
        k_erel<<<NREL, DD>>>(rel_emb, We + wo, be + bo);
        k_qkvs_mma<<<(NN + 127) / 128, 256, SM_TOT>>>(x, bq + bo, bk + bo, bv + bo, bs + bo, l);
        k_attn<<<NN / 8, 256>>>(x, lng + bo, lnb + bo, l == NLAYER - 1);
    }

    k_final<<<1, DD>>>(gout);
}

// round 6
// speedup vs baseline: 1.8444x; 1.1091x over previous
#include <cuda_runtime.h>
#include <cuda_fp16.h>
#include <cstdint>

#define NN 100000
#define NE 600000
#define DD 128
#define NREL 1000
#define NLAYER 3
#define SCAN_B 1024
#define SCAN_NB ((NN + SCAN_B - 1) / SCAN_B)

// ---------------- scratch (static device globals; no allocs) ----------------
__device__ float g_Q[NN * DD];
__device__ float g_KV[NN * 256];  // per node: K row [0..127] then V row [128..255]
__device__ float g_S[NN * DD];
__device__ float g_Erel[NREL * DD];
__device__ float g_gsum[DD];
__device__ int g_cnt[NN];
__device__ int g_incl[NN];
__device__ int g_part[SCAN_NB];
__device__ int g_rowptr[NN + 1];
__device__ int g_cursor[NN + 1];
__device__ int2 g_edge2[NE];  // dst-sorted (src, etype)
// pre-swizzled fp16 W images: 12 (3 layers x {Q,K,V,S}), hi and lo parts
__device__ __align__(16) unsigned char g_WimgH[12 * 32768];
__device__ __align__(16) unsigned char g_WimgL[12 * 32768];

__device__ __forceinline__ uint32_t smem_u32(const void* p) {
    uint32_t a;
    asm("{ .reg .u64 t; cvta.to.shared.u64 t, %1; cvt.u32.u64 %0, t; }" : "=r"(a) : "l"(p));
    return a;
}
__device__ __forceinline__ int swz(int row, int g16) {
    return row * 256 + ((g16 ^ (row & 7)) << 4);
}
__device__ __forceinline__ void ldm_x4(uint32_t& r0, uint32_t& r1, uint32_t& r2, uint32_t& r3,
                                       uint32_t addr) {
    asm volatile("ldmatrix.sync.aligned.m8n8.x4.shared.b16 {%0,%1,%2,%3}, [%4];"
                 : "=r"(r0), "=r"(r1), "=r"(r2), "=r"(r3)
                 : "r"(addr));
}
__device__ __forceinline__ void ldm_x4t(uint32_t& r0, uint32_t& r1, uint32_t& r2, uint32_t& r3,
                                        uint32_t addr) {
    asm volatile("ldmatrix.sync.aligned.m8n8.x4.trans.shared.b16 {%0,%1,%2,%3}, [%4];"
                 : "=r"(r0), "=r"(r1), "=r"(r2), "=r"(r3)
                 : "r"(addr));
}
__device__ __forceinline__ void mma_f16(float* c, const uint32_t* a, uint32_t b0, uint32_t b1) {
    asm volatile(
        "mma.sync.aligned.m16n8k16.row.col.f32.f16.f16.f32 "
        "{%0,%1,%2,%3}, {%4,%5,%6,%7}, {%8,%9}, {%0,%1,%2,%3};"
        : "+f"(c[0]), "+f"(c[1]), "+f"(c[2]), "+f"(c[3])
        : "r"(a[0]), "r"(a[1]), "r"(a[2]), "r"(a[3]), "r"(b0), "r"(b1));
}
__device__ __forceinline__ void cpa16(uint32_t dst, const void* src) {
    asm volatile("cp.async.cg.shared.global [%0], [%1], 16;" ::"r"(dst), "l"(src));
}
__device__ __forceinline__ void cpa_commit() {
    asm volatile("cp.async.commit_group;" ::: "memory");
}
template <int N>
__device__ __forceinline__ void cpa_wait() {
    asm volatile("cp.async.wait_group %0;" ::"n"(N) : "memory");
}

// ---------------- init: x = ent_emb[node_ids] ----------------
__global__ void k_gather(const int* __restrict__ ids, const float* __restrict__ emb,
                         float* __restrict__ x) {
    int i = blockIdx.x * blockDim.x + threadIdx.x;
    if (i >= NN * 32) return;
    int n = i >> 5, l = i & 31;
    ((float4*)x)[n * 32 + l] = ((const float4*)emb)[(long long)ids[n] * 32 + l];
}

__global__ void k_zero() {
    int i = blockIdx.x * blockDim.x + threadIdx.x;
    if (i < NN) g_cnt[i] = 0;
    if (i < DD) g_gsum[i] = 0.f;
}

// ---------------- CSR build (dst-sorted) ----------------
__global__ void k_count(const int* __restrict__ dst) {
    int e = blockIdx.x * blockDim.x + threadIdx.x;
    if (e < NE) atomicAdd(&g_cnt[dst[e]], 1);
}

__global__ void k_scan1() {
    __shared__ int sh[SCAN_B];
    int i = blockIdx.x * SCAN_B + threadIdx.x;
    int v = (i < NN) ? g_cnt[i] : 0;
    sh[threadIdx.x] = v;
    __syncthreads();
    for (int off = 1; off < SCAN_B; off <<= 1) {
        int t = (threadIdx.x >= off) ? sh[threadIdx.x - off] : 0;
        __syncthreads();
        sh[threadIdx.x] += t;
        __syncthreads();
    }
    if (i < NN) g_incl[i] = sh[threadIdx.x];
    if (threadIdx.x == SCAN_B - 1) g_part[blockIdx.x] = sh[SCAN_B - 1];
}

__global__ void k_scan2() {
    if (threadIdx.x == 0 && blockIdx.x == 0) {
        int run = 0;
        for (int b = 0; b < SCAN_NB; b++) {
            int t = g_part[b];
            g_part[b] = run;
            run += t;
        }
    }
}

__global__ void k_scan3() {
    int i = blockIdx.x * SCAN_B + threadIdx.x;
    if (i < NN) {
        int v = g_incl[i] + g_part[blockIdx.x];
        g_rowptr[i + 1] = v;
        g_cursor[i + 1] = v;
        if (i == 0) { g_rowptr[0] = 0; g_cursor[0] = 0; }
    }
}

__global__ void k_scatter(const int* __restrict__ src, const int* __restrict__ dst,
                          const int* __restrict__ etype) {
    int e = blockIdx.x * blockDim.x + threadIdx.x;
    if (e < NE) {
        int p = atomicAdd(&g_cursor[dst[e]], 1);
        g_edge2[p] = make_int2(src[e], etype[e]);
    }
}

// ---------------- once: W -> pre-swizzled fp16 hi/lo images ----------------
__global__ void k_wconv(const float* __restrict__ Wq, const float* __restrict__ Wk,
                        const float* __restrict__ Wv, const float* __restrict__ Ws) {
    int img = blockIdx.x;  // 0..11
    int l = img >> 2, m = img & 3;
    const float* W =
        ((m == 0) ? Wq : (m == 1) ? Wk : (m == 2) ? Wv : Ws) + (long long)l * DD * DD;
    unsigned char* hi = g_WimgH + img * 32768;
    unsigned char* lo = g_WimgL + img * 32768;
    for (int i = threadIdx.x; i < DD * DD; i += blockDim.x) {
        int k = i >> 7, n = i & 127;  // B(k,n) = W[k][n]
        float w = W[k * DD + n];
        __half h = __float2half(w);
        __half l2 = __float2half(w - __half2float(h));
        int o = swz(k, n >> 3) + (n & 7) * 2;
        *(__half*)(hi + o) = h;
        *(__half*)(lo + o) = l2;
    }
}

// ---------------- per-layer: relation projection table (1000x128) ----------------
__global__ void k_erel(const float* __restrict__ rel, const float* __restrict__ We,
                       const float* __restrict__ be) {
    __shared__ float sr[DD];
    int r = blockIdx.x, j = threadIdx.x;
    sr[j] = rel[r * DD + j];
    __syncthreads();
    float acc = be[j];
#pragma unroll 8
    for (int i = 0; i < DD; i++) acc = fmaf(sr[i], We[i * DD + j], acc);
    g_Erel[r * DD + j] = acc;
}

// ---------------- mma.sync fused Q/K/V/Skip GEMM (fp16 A + split-fp16 B) ------
// smem: bias 2KB | A fp16 32KB | B hi/lo 64KB  => 98KB -> 2 CTA/SM
#define SM_BIAS 0
#define SM_A 2048
#define SM_B (SM_A + 32768)
#define SM_TOT (SM_B + 65536)

__device__ __forceinline__ void copyB_async(uint32_t sbdst, int img, int t) {
    const unsigned char* sh = g_WimgH + img * 32768;
    const unsigned char* sl = g_WimgL + img * 32768;
#pragma unroll
    for (int i = 0; i < 8; i++) {
        int o = (t + i * 256) * 16;
        cpa16(sbdst + o, sh + o);
        cpa16(sbdst + 32768 + o, sl + o);
    }
}

__global__ void __launch_bounds__(256, 2)
k_qkvs_mma(const float* __restrict__ x, const float* __restrict__ bq,
           const float* __restrict__ bk, const float* __restrict__ bv,
           const float* __restrict__ bs, int layer) {
    extern __shared__ unsigned char smem[];
    uint32_t sb = smem_u32(smem);
    int t = threadIdx.x, w = t >> 5, lane = t & 31;
    int wr = w & 3, wc = w >> 2;  // 4 row-groups x 2 col-groups
    int rowBase = blockIdx.x * 128;

    copyB_async(sb + SM_B, layer * 4 + 0, t);
    cpa_commit();

    if (t < 128) {
        float* bsm = (float*)(smem + SM_BIAS);
        bsm[t] = bq[t];
        bsm[128 + t] = bk[t];
        bsm[256 + t] = bv[t];
        bsm[384 + t] = bs[t];
    }

    // A tile: fp32 x -> fp16, swizzled smem
#pragma unroll
    for (int it = 0; it < 16; it++) {
        int f4 = t + it * 256;
        int r = f4 >> 5, c4 = (f4 & 31) << 2;
        float4 v = make_float4(0.f, 0.f, 0.f, 0.f);
        if (rowBase + r < NN) v = *(const float4*)&x[(long long)(rowBase + r) * 128 + c4];
        uint2 hp;
        __half2 h01 = __floats2half2_rn(v.x, v.y);
        __half2 h23 = __floats2half2_rn(v.z, v.w);
        hp.x = *(uint32_t*)&h01;
        hp.y = *(uint32_t*)&h23;
        int o = swz(r, c4 >> 3) + (c4 & 7) * 2;
        *(uint2*)(smem + SM_A + o) = hp;
    }

    for (int mi = 0; mi < 4; mi++) {
        cpa_wait<0>();
        __syncthreads();  // B(mi) visible to all warps

        float acc[2][8][4];
#pragma unroll
        for (int a = 0; a < 2; a++)
#pragma unroll
            for (int i = 0; i < 8; i++)
#pragma unroll
                for (int j = 0; j < 4; j++) acc[a][i][j] = 0.f;

        int arow0 = wr * 32 + (lane & 15);
        int bmat = lane >> 3;
        int brow_in = ((bmat & 1) << 3) + (lane & 7);
        int bghalf = bmat >> 1;

#pragma unroll
        for (int ks = 0; ks < 8; ks++) {
            uint32_t ah[2][4];
            int ag = ks * 2 + (lane >> 4);
#pragma unroll
            for (int mt = 0; mt < 2; mt++) {
                uint32_t aaddr = sb + SM_A + swz(arow0 + mt * 16, ag);
                ldm_x4(ah[mt][0], ah[mt][1], ah[mt][2], ah[mt][3], aaddr);
            }
            int brow = ks * 16 + brow_in;
            uint32_t bh[4][4], bl[4][4];
#pragma unroll
            for (int np = 0; np < 4; np++) {
                uint32_t baddr = sb + SM_B + swz(brow, wc * 8 + np * 2 + bghalf);
                ldm_x4t(bh[np][0], bh[np][1], bh[np][2], bh[np][3], baddr);
                ldm_x4t(bl[np][0], bl[np][1], bl[np][2], bl[np][3], baddr + 32768);
            }
            // term 1: A * Bh
#pragma unroll
            for (int np = 0; np < 4; np++)
#pragma unroll
                for (int mt = 0; mt < 2; mt++) {
                    mma_f16(acc[mt][np * 2], ah[mt], bh[np][0], bh[np][1]);
                    mma_f16(acc[mt][np * 2 + 1], ah[mt], bh[np][2], bh[np][3]);
                }
            // term 2: A * Bl
#pragma unroll
            for (int np = 0; np < 4; np++)
#pragma unroll
                for (int mt = 0; mt < 2; mt++) {
                    mma_f16(acc[mt][np * 2], ah[mt], bl[np][0], bl[np][1]);
                    mma_f16(acc[mt][np * 2 + 1], ah[mt], bl[np][2], bl[np][3]);
                }
        }

        // all warps done reading B(mi); start streaming B(mi+1) under the epilogue
        __syncthreads();
        if (mi < 3) {
            copyB_async(sb + SM_B, layer * 4 + mi + 1, t);
            cpa_commit();
        }

        // epilogue; K/V interleave into g_KV (K at +0, V at +128; row stride 256)
        float* outp;
        int rstride;
        if (mi == 0) { outp = g_Q; rstride = 128; }
        else if (mi == 1) { outp = g_KV; rstride = 256; }
        else if (mi == 2) { outp = g_KV + 128; rstride = 256; }
        else { outp = g_S; rstride = 128; }
        const float* bsm = (const float*)(smem + SM_BIAS) + mi * 128;
        int cb = wc * 64 + (lane & 3) * 2;
#pragma unroll
        for (int mt = 0; mt < 2; mt++) {
            int r0 = rowBase + wr * 32 + mt * 16 + (lane >> 2);
#pragma unroll
            for (int nt = 0; nt < 8; nt++) {
                int col = cb + nt * 8;
                float2 b2 = make_float2(bsm[col], bsm[col + 1]);
                if (r0 < NN) {
                    float2 o0 = make_float2(acc[mt][nt][0] + b2.x, acc[mt][nt][1] + b2.y);
                    *(float2*)&outp[(long long)r0 * rstride + col] = o0;
                }
                if (r0 + 8 < NN) {
                    float2 o1 = make_float2(acc[mt][nt][2] + b2.x, acc[mt][nt][3] + b2.y);
                    *(float2*)&outp[(long long)(r0 + 8) * rstride + col] = o1;
                }
            }
        }
    }
}

// ---------------- fused attention / softmax / aggregate / LN / residual ----------------
// NN = 100000 = 12500 blocks * 8 warps exactly.
__global__ void k_attn(float* __restrict__ x, const float* __restrict__ lng,
                       const float* __restrict__ lnb, int last) {
    __shared__ float sums[DD];
    int n = blockIdx.x * (blockDim.x >> 5) + (threadIdx.x >> 5);
    int lane = threadIdx.x & 31;

    const float4* Q4 = (const float4*)g_Q;
    const float4* KV4 = (const float4*)g_KV;
    const float4* E4 = (const float4*)g_Erel;

    float4 q = Q4[n * 32 + lane];
    int beg = g_rowptr[n], end = g_rowptr[n + 1];

    float m = -3.4e38f, dsum = 0.f;
    float4 acc = make_float4(0.f, 0.f, 0.f, 0.f);

    int idx = beg;
#define EDGE_LOAD(i, e)                         \
    float4 kv##i = KV4[(e).x * 64 + lane];      \
    float4 vv##i = KV4[(e).x * 64 + 32 + lane]; \
    float4 ev##i = E4[(e).y * 32 + lane];
#define EDGE_DOT(i)                                                      \
    float p##i = q.x * (kv##i.x + ev##i.x) + q.y * (kv##i.y + ev##i.y) + \
                 q.z * (kv##i.z + ev##i.z) + q.w * (kv##i.w + ev##i.w);  \
    p##i += __shfl_xor_sync(0xffffffffu, p##i, 1);                       \
    p##i += __shfl_xor_sync(0xffffffffu, p##i, 2);                       \
    float a##i = p##i * 0.25f;
#define EDGE_ACC(i)                      \
    acc.x += w##i * (vv##i.x + ev##i.x); \
    acc.y += w##i * (vv##i.y + ev##i.y); \
    acc.z += w##i * (vv##i.z + ev##i.z); \
    acc.w += w##i * (vv##i.w + ev##i.w);

    for (; idx + 3 < end; idx += 4) {
        int2 e0 = g_edge2[idx];
        int2 e1 = g_edge2[idx + 1];
        int2 e2 = g_edge2[idx + 2];
        int2 e3 = g_edge2[idx + 3];
        EDGE_LOAD(0, e0) EDGE_LOAD(1, e1) EDGE_LOAD(2, e2) EDGE_LOAD(3, e3)
        EDGE_DOT(0) EDGE_DOT(1) EDGE_DOT(2) EDGE_DOT(3)
        float mn = fmaxf(fmaxf(m, fmaxf(a0, a1)), fmaxf(a2, a3));
        float sc = __expf(m - mn);
        float w0 = __expf(a0 - mn), w1 = __expf(a1 - mn);
        float w2 = __expf(a2 - mn), w3 = __expf(a3 - mn);
        dsum = dsum * sc + w0 + w1 + w2 + w3;
        acc.x *= sc; acc.y *= sc; acc.z *= sc; acc.w *= sc;
        EDGE_ACC(0) EDGE_ACC(1) EDGE_ACC(2) EDGE_ACC(3)
        m = mn;
    }
    for (; idx < end; idx++) {
        int2 e0 = g_edge2[idx];
        EDGE_LOAD(0, e0)
        EDGE_DOT(0)
        float mn = fmaxf(m, a0);
        float sc = __expf(m - mn);
        float w0 = __expf(a0 - mn);
        dsum = dsum * sc + w0;
        acc.x *= sc; acc.y *= sc; acc.z *= sc; acc.w *= sc;
        EDGE_ACC(0)
        m = mn;
    }

    float inv = (dsum > 0.f) ? (1.f / dsum) : 0.f;
    float4 sk = ((const float4*)g_S)[n * 32 + lane];
    float4 o = make_float4(acc.x * inv + sk.x, acc.y * inv + sk.y, acc.z * inv + sk.z,
                           acc.w * inv + sk.w);

    float sum = o.x + o.y + o.z + o.w;
#pragma unroll
    for (int off = 16; off; off >>= 1) sum += __shfl_xor_sync(0xffffffffu, sum, off);
    float mean = sum * (1.f / 128.f);
    float4 c = make_float4(o.x - mean, o.y - mean, o.z - mean, o.w - mean);
    float ss = c.x * c.x + c.y * c.y + c.z * c.z + c.w * c.w;
#pragma unroll
    for (int off = 16; off; off >>= 1) ss += __shfl_xor_sync(0xffffffffu, ss, off);
    float var = ss * (1.f / 128.f);
    float rstd = rsqrtf(var + 1e-5f);

    float4 g = ((const float4*)lng)[lane];
    float4 b = ((const float4*)lnb)[lane];
    float4 y;
    y.x = fmaxf(c.x * rstd * g.x + b.x, 0.f);
    y.y = fmaxf(c.y * rstd * g.y + b.y, 0.f);
    y.z = fmaxf(c.z * rstd * g.z + b.z, 0.f);
    y.w = fmaxf(c.w * rstd * g.w + b.w, 0.f);

    float4 xo = ((float4*)x)[n * 32 + lane];
    xo.x += y.x;
    xo.y += y.y;
    xo.z += y.z;
    xo.w += y.w;
    ((float4*)x)[n * 32 + lane] = xo;

    if (last) {  // fold graph-mean column sums into last layer
        if (threadIdx.x < DD) sums[threadIdx.x] = 0.f;
        __syncthreads();
        atomicAdd(&sums[lane * 4 + 0], xo.x);
        atomicAdd(&sums[lane * 4 + 1], xo.y);
        atomicAdd(&sums[lane * 4 + 2], xo.z);
        atomicAdd(&sums[lane * 4 + 3], xo.w);
        __syncthreads();
        if (threadIdx.x < DD) atomicAdd(&g_gsum[threadIdx.x], sums[threadIdx.x]);
    }
}

__global__ void k_final(float* __restrict__ gout) {
    int c = threadIdx.x;
    if (c < DD) gout[c] = g_gsum[c] * (1.f / (float)NN);
}

// ---------------- launch ----------------
extern "C" void kernel_launch(void* const* d_in, const int* in_sizes, int n_in,
                              void* d_out, int out_size) {
    const int* node_ids = (const int*)d_in[0];
    const int* edge_index = (const int*)d_in[1];
    const int* edge_type = (const int*)d_in[2];
    const float* ent_emb = (const float*)d_in[3];
    const float* rel_emb = (const float*)d_in[4];
    const float* Wq = (const float*)d_in[5];
    const float* bq = (const float*)d_in[6];
    const float* Wk = (const float*)d_in[7];
    const float* bk = (const float*)d_in[8];
    const float* Wv = (const float*)d_in[9];
    const float* bv = (const float*)d_in[10];
    const float* We = (const float*)d_in[11];
    const float* be = (const float*)d_in[12];
    const float* Ws = (const float*)d_in[13];
    const float* bs = (const float*)d_in[14];
    const float* lng = (const float*)d_in[15];
    const float* lnb = (const float*)d_in[16];

    float* x = (float*)d_out;
    float* gout = (float*)d_out + (out_size - DD);

    const int* src = edge_index;
    const int* dst = edge_index + NE;

    cudaFuncSetAttribute(k_qkvs_mma, cudaFuncAttributeMaxDynamicSharedMemorySize, SM_TOT);

    // launches 1-4: put layer-0 GEMM in the ncu capture slot (4th launch)
    k_gather<<<(NN * 32 + 255) / 256, 256>>>(node_ids, ent_emb, x);
    k_wconv<<<12, 256>>>(Wq, Wk, Wv, Ws);
    k_erel<<<NREL, DD>>>(rel_emb, We, be);
    k_qkvs_mma<<<(NN + 127) / 128, 256, SM_TOT>>>(x, bq, bk, bv, bs, 0);

    // CSR build (needed before first k_attn)
    k_zero<<<(NN + 255) / 256, 256>>>();
    k_count<<<(NE + 255) / 256, 256>>>(dst);
    k_scan1<<<SCAN_NB, SCAN_B>>>();
    k_scan2<<<1, 32>>>();
    k_scan3<<<SCAN_NB, SCAN_B>>>();
    k_scatter<<<(NE + 255) / 256, 256>>>(src, dst, edge_type);

    k_attn<<<NN / 8, 256>>>(x, lng, lnb, 0);

    for (int l = 1; l < NLAYER; l++) {
        long long wo = (long long)l * DD * DD;
        int bo = l * DD;
        k_erel<<<NREL, DD>>>(rel_emb, We + wo, be + bo);
        k_qkvs_mma<<<(NN + 127) / 128, 256, SM_TOT>>>(x, bq + bo, bk + bo, bv + bo, bs + bo, l);
        k_attn<<<NN / 8, 256>>>(x, lng + bo, lnb + bo, l == NLAYER - 1);
    }

    k_final<<<1, DD>>>(gout);
}